// round 12
// baseline (speedup 1.0000x reference)
#include <cuda_runtime.h>
#include <cuda_bf16.h>
#include <math.h>
#include <stdint.h>

// Problem constants (B=2, S=2048, D=1024; fixed-shape problem)
#define D_DIM   1024
#define NQK     4096
#define NV      4096
#define NKNOW   8192
#define NTOT    (NQK + NV + NKNOW)   // 16384
#define MROWS   4096                 // B*S
#define KSPLIT  3072                 // 3 x 1024 bf16-split K

#define BAND_RAW 3.1e-5f
#define THR_MIN  2e-4f
#define MAX_BAND 64
#define FIX_CAP  65536

// ---------------- scratch ----------------
__device__ float g_scores[(size_t)MROWS * NTOT];            // 268 MB
__device__ __nv_bfloat16 g_Abf[(size_t)MROWS * KSPLIT];     // 25 MB  [hi | lo | hi]
__device__ __nv_bfloat16 g_Bbf[(size_t)NTOT * KSPLIT];      // 100 MB [hi | hi | lo]
__device__ float g_tau[MROWS * 4];
__device__ float g_colsum[NTOT + NKNOW];
__device__ int   g_fix_cnt;
__device__ int   g_fix_items[FIX_CAP];

// ======================= PTX helpers (plain sm_103-safe) =======================
__device__ __forceinline__ uint32_t smem_u32(const void* p) {
    uint32_t a;
    asm("{ .reg .u64 t; cvta.to.shared.u64 t, %1; cvt.u32.u64 %0, t; }" : "=r"(a) : "l"(p));
    return a;
}
#define CP_ASYNC16(dst, src) \
    asm volatile("cp.async.cg.shared.global [%0], [%1], 16;" :: "r"(dst), "l"(src))
#define CP_COMMIT() asm volatile("cp.async.commit_group;")

__device__ __forceinline__ void ldmatrix_x4(uint32_t& r0, uint32_t& r1, uint32_t& r2, uint32_t& r3, uint32_t addr) {
    asm volatile("ldmatrix.sync.aligned.m8n8.x4.shared.b16 {%0,%1,%2,%3}, [%4];"
                 : "=r"(r0), "=r"(r1), "=r"(r2), "=r"(r3) : "r"(addr));
}
__device__ __forceinline__ void ldmatrix_x2(uint32_t& r0, uint32_t& r1, uint32_t addr) {
    asm volatile("ldmatrix.sync.aligned.m8n8.x2.shared.b16 {%0,%1}, [%2];"
                 : "=r"(r0), "=r"(r1) : "r"(addr));
}
__device__ __forceinline__ void mma_bf16(float* c, const uint32_t* a, const uint32_t* b) {
    asm volatile("mma.sync.aligned.m16n8k16.row.col.f32.bf16.bf16.f32 "
                 "{%0,%1,%2,%3}, {%4,%5,%6,%7}, {%8,%9}, {%0,%1,%2,%3};"
                 : "+f"(c[0]), "+f"(c[1]), "+f"(c[2]), "+f"(c[3])
                 : "r"(a[0]), "r"(a[1]), "r"(a[2]), "r"(a[3]), "r"(b[0]), "r"(b[1]));
}

// ---------------- init (colsums + fix counter; out zeroed by memset) ----------------
__global__ void init_kernel() {
    int i = blockIdx.x * blockDim.x + threadIdx.x;
    if (i < NTOT + NKNOW) g_colsum[i] = 0.f;
    if (i == 0) g_fix_cnt = 0;
}

// ---------------- bf16-split conversion ----------------
__global__ __launch_bounds__(256) void convertA_kernel(const float* __restrict__ x) {
    int i = blockIdx.x * 256 + threadIdx.x;
    float4 v = ((const float4*)x)[i];
    int m = i >> 8;
    int k4 = (i & 255) << 2;
    __nv_bfloat16 h0 = __float2bfloat16(v.x), h1 = __float2bfloat16(v.y);
    __nv_bfloat16 h2 = __float2bfloat16(v.z), h3 = __float2bfloat16(v.w);
    __nv_bfloat16 l0 = __float2bfloat16(v.x - __bfloat162float(h0));
    __nv_bfloat16 l1 = __float2bfloat16(v.y - __bfloat162float(h1));
    __nv_bfloat16 l2 = __float2bfloat16(v.z - __bfloat162float(h2));
    __nv_bfloat16 l3 = __float2bfloat16(v.w - __bfloat162float(h3));
    __nv_bfloat16* base = g_Abf + (size_t)m * KSPLIT + k4;
    ((__nv_bfloat162*)(base))[0]        = __halves2bfloat162(h0, h1);
    ((__nv_bfloat162*)(base))[1]        = __halves2bfloat162(h2, h3);
    ((__nv_bfloat162*)(base + 1024))[0] = __halves2bfloat162(l0, l1);
    ((__nv_bfloat162*)(base + 1024))[1] = __halves2bfloat162(l2, l3);
    ((__nv_bfloat162*)(base + 2048))[0] = __halves2bfloat162(h0, h1);
    ((__nv_bfloat162*)(base + 2048))[1] = __halves2bfloat162(h2, h3);
}

__global__ __launch_bounds__(256) void convertB_kernel(
    const float* __restrict__ qk, const float* __restrict__ vem, const float* __restrict__ knm) {
    int i = blockIdx.x * 256 + threadIdx.x;
    int n = i >> 8;
    int k4 = (i & 255) << 2;
    const float* src;
    if (n < NQK)            src = qk  + (size_t)n * D_DIM;
    else if (n < NQK + NV)  src = vem + (size_t)(n - NQK) * D_DIM;
    else                    src = knm + (size_t)(n - NQK - NV) * D_DIM;
    float4 v = *(const float4*)(src + k4);
    __nv_bfloat16 h0 = __float2bfloat16(v.x), h1 = __float2bfloat16(v.y);
    __nv_bfloat16 h2 = __float2bfloat16(v.z), h3 = __float2bfloat16(v.w);
    __nv_bfloat16 l0 = __float2bfloat16(v.x - __bfloat162float(h0));
    __nv_bfloat16 l1 = __float2bfloat16(v.y - __bfloat162float(h1));
    __nv_bfloat16 l2 = __float2bfloat16(v.z - __bfloat162float(h2));
    __nv_bfloat16 l3 = __float2bfloat16(v.w - __bfloat162float(h3));
    __nv_bfloat16* base = g_Bbf + (size_t)n * KSPLIT + k4;
    ((__nv_bfloat162*)(base))[0]        = __halves2bfloat162(h0, h1);
    ((__nv_bfloat162*)(base))[1]        = __halves2bfloat162(h2, h3);
    ((__nv_bfloat162*)(base + 1024))[0] = __halves2bfloat162(h0, h1);
    ((__nv_bfloat162*)(base + 1024))[1] = __halves2bfloat162(h2, h3);
    ((__nv_bfloat162*)(base + 2048))[0] = __halves2bfloat162(l0, l1);
    ((__nv_bfloat162*)(base + 2048))[1] = __halves2bfloat162(l2, l3);
}

// ---------------- tau kernel ----------------
__global__ __launch_bounds__(128) void tau_kernel(
    const float* __restrict__ x,
    const float* __restrict__ w_attn, const float* __restrict__ b_attn,
    const float* __restrict__ w_know, const float* __restrict__ b_know)
{
    int r = blockIdx.x;
    const float* xr = x + (size_t)r * D_DIM;
    float s0 = 0.f, s1 = 0.f, s2 = 0.f, s3 = 0.f;
    for (int d = threadIdx.x; d < D_DIM; d += 128) {
        float xv = xr[d];
        s0 += xv * w_attn[d * 3 + 0];
        s1 += xv * w_attn[d * 3 + 1];
        s2 += xv * w_attn[d * 3 + 2];
        s3 += xv * w_know[d];
    }
    __shared__ float red[4][128];
    red[0][threadIdx.x] = s0; red[1][threadIdx.x] = s1;
    red[2][threadIdx.x] = s2; red[3][threadIdx.x] = s3;
    __syncthreads();
    for (int off = 64; off > 0; off >>= 1) {
        if (threadIdx.x < off) {
            red[0][threadIdx.x] += red[0][threadIdx.x + off];
            red[1][threadIdx.x] += red[1][threadIdx.x + off];
            red[2][threadIdx.x] += red[2][threadIdx.x + off];
            red[3][threadIdx.x] += red[3][threadIdx.x + off];
        }
        __syncthreads();
    }
    if (threadIdx.x == 0) {
        g_tau[r * 4 + 0] = red[0][0] + b_attn[0];
        g_tau[r * 4 + 1] = red[1][0] + b_attn[1];
        g_tau[r * 4 + 2] = red[2][0] + b_attn[2];
        g_tau[r * 4 + 3] = red[3][0] + b_know[0];
    }
}

// ---------------- mma.sync bf16 GEMM (exact R4 champion config) ----------------
#define STG_SZ  20480                 // A (10240) + B (10240) per stage
#define NSTAGE  3
#define KITERS  (KSPLIT / 32)         // 96
#define GEMM_SMEM (NSTAGE * STG_SZ)   // 61440

__device__ __forceinline__ void gemm_load_stage(uint32_t sbase,
    const __nv_bfloat16* gA, const __nv_bfloat16* gB, int kit, int s, int tid)
{
    const int k0 = kit * 32;
    const uint32_t st = sbase + s * STG_SZ;
#pragma unroll
    for (int i = 0; i < 2; i++) {
        int c = tid + i * 256;
        int row = c >> 2, c4 = c & 3;
        CP_ASYNC16(st + row * 80 + c4 * 16,
                   gA + (size_t)row * KSPLIT + k0 + c4 * 8);
    }
#pragma unroll
    for (int i = 0; i < 2; i++) {
        int c = tid + i * 256;
        int row = c >> 2, c4 = c & 3;
        CP_ASYNC16(st + 10240 + row * 80 + c4 * 16,
                   gB + (size_t)row * KSPLIT + k0 + c4 * 8);
    }
}

__global__ __launch_bounds__(256, 2) void gemm_bf16_kernel() {
    extern __shared__ __align__(128) char smem[];
    const uint32_t sbase = smem_u32(smem);
    const int tid = threadIdx.x;
    const int wid = tid >> 5;
    const int lid = tid & 31;
    const int m0 = blockIdx.x * 128;
    const int n0 = blockIdx.y * 128;
    const int wm = wid & 1;
    const int wn = wid >> 1;

    const __nv_bfloat16* gA = g_Abf + (size_t)m0 * KSPLIT;
    const __nv_bfloat16* gB = g_Bbf + (size_t)n0 * KSPLIT;

    const int arow = (lid & 7) + ((lid >> 3) & 1) * 8;
    const int acol = (lid >> 4) * 8;
    const int brow = lid & 7;
    const int bcol = ((lid >> 3) & 1) * 8;

    float acc[4][4][4];
#pragma unroll
    for (int i = 0; i < 4; i++)
#pragma unroll
        for (int j = 0; j < 4; j++)
#pragma unroll
            for (int q = 0; q < 4; q++) acc[i][j][q] = 0.f;

    gemm_load_stage(sbase, gA, gB, 0, 0, tid); CP_COMMIT();
    gemm_load_stage(sbase, gA, gB, 1, 1, tid); CP_COMMIT();

#pragma unroll 1
    for (int k = 0; k < KITERS; k++) {
        const int s = k % NSTAGE;
        if (k < KITERS - 2) asm volatile("cp.async.wait_group 1;");
        else                asm volatile("cp.async.wait_group 0;");
        __syncthreads();

        const uint32_t sA = sbase + s * STG_SZ;
        const uint32_t sB = sA + 10240;
#pragma unroll
        for (int ks = 0; ks < 2; ks++) {
            const int kb = ks * 16;
            uint32_t a[4][4], b[4][2];
            const uint32_t a_base = sA + (uint32_t)(wm * 64 + arow) * 80u + (uint32_t)(kb + acol) * 2u;
#pragma unroll
            for (int i = 0; i < 4; i++)
                ldmatrix_x4(a[i][0], a[i][1], a[i][2], a[i][3], a_base + (uint32_t)(i * 16 * 80));
            const uint32_t b_base = sB + (uint32_t)(wn * 32 + brow) * 80u + (uint32_t)(kb + bcol) * 2u;
#pragma unroll
            for (int j = 0; j < 4; j++)
                ldmatrix_x2(b[j][0], b[j][1], b_base + (uint32_t)(j * 8 * 80));
#pragma unroll
            for (int i = 0; i < 4; i++)
#pragma unroll
                for (int j = 0; j < 4; j++)
                    mma_bf16(acc[i][j], a[i], b[j]);
        }

        if (k + 2 < KITERS) {
            gemm_load_stage(sbase, gA, gB, k + 2, (k + 2) % NSTAGE, tid);
            CP_COMMIT();
        }
    }

    const int r4 = lid >> 2;
    const int c2 = (lid & 3) * 2;
#pragma unroll
    for (int i = 0; i < 4; i++) {
#pragma unroll
        for (int j = 0; j < 4; j++) {
            int row = m0 + wm * 64 + i * 16 + r4;
            int col = n0 + wn * 32 + j * 8 + c2;
            float* p0 = g_scores + (size_t)row * NTOT + col;
            float* p1 = g_scores + (size_t)(row + 8) * NTOT + col;
            *(float2*)p0 = make_float2(acc[i][j][0], acc[i][j][1]);
            *(float2*)p1 = make_float2(acc[i][j][2], acc[i][j][3]);
        }
    }
}

// ---------------- gate kernel (R4 champion + sparse stores; zeros pre-memset) ----------------
__global__ __launch_bounds__(256) void gate_kernel(
    int seg_off, int N, int ksel, int tau_idx, int gate_id,
    float* __restrict__ out, int colsum_off)
{
    const int r = blockIdx.x;
    const float* s = g_scores + (size_t)r * NTOT + seg_off;
    const float tauv = g_tau[r * 4 + tau_idx];

    __shared__ float eg[NKNOW];
    __shared__ unsigned hist[256];
    __shared__ float red[256];
    __shared__ unsigned sh_sel;
    __shared__ int sh_kneed;
    __shared__ int sh_bandcnt;
    const int tid = threadIdx.x;

    float lmax = 0.f;
    for (int i = tid; i < N; i += 256) {
        float raw = s[i] - tauv;
        float e = (raw > 0.f) ? (expf(raw) - 1.f) : 0.f;
        eg[i] = e;
        lmax = fmaxf(lmax, e);
    }
    red[tid] = lmax; __syncthreads();
    for (int off = 128; off > 0; off >>= 1) {
        if (tid < off) red[tid] = fmaxf(red[tid], red[tid + off]);
        __syncthreads();
    }
    const float gmax = red[0];
    __syncthreads();

    // radix select: exact k-th largest
    unsigned prefix = 0u, mask = 0u;
    int kneed = ksel;
    for (int shift = 24; shift >= 0; shift -= 8) {
        hist[tid] = 0u;
        __syncthreads();
        for (int i = tid; i < N; i += 256) {
            unsigned b = __float_as_uint(eg[i]);
            if ((b & mask) == prefix) atomicAdd(&hist[(b >> shift) & 0xFFu], 1u);
        }
        __syncthreads();
        if (tid == 0) {
            unsigned cum = 0u; int sel = 0; int newk = kneed;
            for (int bin = 255; bin >= 0; bin--) {
                unsigned h = hist[bin];
                if (cum + h >= (unsigned)kneed) { sel = bin; newk = kneed - (int)cum; break; }
                cum += h;
            }
            sh_sel = (unsigned)sel; sh_kneed = newk;
        }
        __syncthreads();
        prefix |= sh_sel << shift;
        mask   |= 0xFFu << shift;
        kneed   = sh_kneed;
        __syncthreads();
    }
    const float thr = __uint_as_float(prefix);

    bool need_fix = false;
    if (thr > THR_MIN) {
        float width = (thr + 1.0f) * BAND_RAW;
        float e_hi = thr + width, e_lo = thr - width;
        if (tid == 0) sh_bandcnt = 0;
        __syncthreads();
        int c = 0;
        for (int i = tid; i < N; i += 256) {
            float e = eg[i];
            if (e >= e_lo && e <= e_hi) c++;
        }
        if (c) atomicAdd(&sh_bandcnt, c);
        __syncthreads();
        need_fix = (sh_bandcnt > 1);
    }

    if (need_fix) {
        if (tid == 0) {
            int idx = atomicAdd(&g_fix_cnt, 1);
            if (idx < FIX_CAP) g_fix_items[idx] = r | (gate_id << 16);
        }
        return;  // fixup kernel rewrites this row (zeros already memset)
    }

    float lsum = 0.f;
    for (int i = tid; i < N; i += 256) {
        float e = eg[i];
        if (e >= thr) lsum += e;
    }
    red[tid] = lsum; __syncthreads();
    for (int off = 128; off > 0; off >>= 1) {
        if (tid < off) red[tid] += red[tid + off];
        __syncthreads();
    }
    const float scale = tanhf(gmax) / (red[0] + 1e-8f);

    // Sparse output: zeros already written by memset; store only kept nonzeros.
    float* orow = out + (size_t)r * N;
    for (int i = tid; i < N; i += 256) {
        float e = eg[i];
        if (e >= thr && e > 0.f) {
            float val = e * scale;
            orow[i] = val;
            atomicAdd(&g_colsum[colsum_off + i], val);
        }
    }
}

// ---------------- radix select for fixup ----------------
__device__ float radix_select_kth(const float* eg, int N, int ksel,
                                  unsigned* hist, unsigned* sh_sel, int* sh_kneed)
{
    const int tid = threadIdx.x;
    unsigned prefix = 0u, mask = 0u;
    int kneed = ksel;
    for (int shift = 24; shift >= 0; shift -= 8) {
        hist[tid] = 0u;
        __syncthreads();
        for (int i = tid; i < N; i += 256) {
            unsigned b = __float_as_uint(eg[i]);
            if ((b & mask) == prefix) atomicAdd(&hist[(b >> shift) & 0xFFu], 1u);
        }
        __syncthreads();
        if (tid == 0) {
            unsigned cum = 0u; int sel = 0; int newk = kneed;
            for (int bin = 255; bin >= 0; bin--) {
                unsigned h = hist[bin];
                if (cum + h >= (unsigned)kneed) { sel = bin; newk = kneed - (int)cum; break; }
                cum += h;
            }
            *sh_sel = (unsigned)sel; *sh_kneed = newk;
        }
        __syncthreads();
        prefix |= (*sh_sel) << shift;
        mask   |= 0xFFu << shift;
        kneed   = *sh_kneed;
        __syncthreads();
    }
    return __uint_as_float(prefix);
}

// ---------------- fixup kernel: exact fp64 re-ranking of ambiguous rows ----------------
__global__ __launch_bounds__(256) void fixup_kernel(
    const float* __restrict__ x,
    const float* __restrict__ qk, const float* __restrict__ vem, const float* __restrict__ knm,
    float* __restrict__ outQ, float* __restrict__ outK,
    float* __restrict__ outV, float* __restrict__ outKn)
{
    __shared__ float eg[NKNOW];
    __shared__ unsigned hist[256];
    __shared__ float red[256];
    __shared__ double dred[256];
    __shared__ unsigned sh_sel;
    __shared__ int sh_kneed;
    __shared__ int bidx[MAX_BAND];
    __shared__ double ds[MAX_BAND];
    __shared__ int keptm[MAX_BAND];
    __shared__ int sh_bc, sh_nhi;
    const int tid = threadIdx.x;

    int nfix = g_fix_cnt; if (nfix > FIX_CAP) nfix = FIX_CAP;

    for (int it = blockIdx.x; it < nfix; it += gridDim.x) {
        int code = g_fix_items[it];
        int r = code & 0xFFFF;
        int gate = code >> 16;

        int seg_off, N, ksel, tau_idx, cs_off;
        const float* emb; float* orow;
        if      (gate == 0) { seg_off = 0;        N = NQK;   ksel = 64;  tau_idx = 0; emb = qk;  orow = outQ;  cs_off = 0; }
        else if (gate == 1) { seg_off = 0;        N = NQK;   ksel = 64;  tau_idx = 1; emb = qk;  orow = outK;  cs_off = NQK; }
        else if (gate == 2) { seg_off = NQK;      N = NV;    ksel = 64;  tau_idx = 2; emb = vem; orow = outV;  cs_off = 2 * NQK; }
        else                { seg_off = NQK + NV; N = NKNOW; ksel = 128; tau_idx = 3; emb = knm; orow = outKn; cs_off = 3 * NQK; }
        orow += (size_t)r * N;

        const float* s = g_scores + (size_t)r * NTOT + seg_off;
        const float tauv = g_tau[r * 4 + tau_idx];

        float lmax = 0.f;
        for (int i = tid; i < N; i += 256) {
            float raw = s[i] - tauv;
            float e = (raw > 0.f) ? (expf(raw) - 1.f) : 0.f;
            eg[i] = e;
            lmax = fmaxf(lmax, e);
        }
        red[tid] = lmax; __syncthreads();
        for (int off = 128; off > 0; off >>= 1) {
            if (tid < off) red[tid] = fmaxf(red[tid], red[tid + off]);
            __syncthreads();
        }
        const float gmax = red[0];
        __syncthreads();

        const float thr = radix_select_kth(eg, N, ksel, hist, &sh_sel, &sh_kneed);
        const float width = (thr + 1.0f) * BAND_RAW;
        const float e_hi = thr + width, e_lo = thr - width;

        if (tid == 0) { sh_bc = 0; sh_nhi = 0; }
        __syncthreads();
        for (int i = tid; i < N; i += 256) {
            float e = eg[i];
            if (e > e_hi) atomicAdd(&sh_nhi, 1);
            else if (e >= e_lo) {
                int p = atomicAdd(&sh_bc, 1);
                if (p < MAX_BAND) bidx[p] = i;
            }
        }
        __syncthreads();
        const int bc = (sh_bc < MAX_BAND) ? sh_bc : MAX_BAND;
        const int nhi = sh_nhi;

        const float* xr = x + (size_t)r * D_DIM;
        for (int b = 0; b < bc; b++) {
            const float* er = emb + (size_t)bidx[b] * D_DIM;
            double part = 0.0;
            for (int d = tid; d < D_DIM; d += 256)
                part += (double)xr[d] * (double)er[d];
            dred[tid] = part; __syncthreads();
            for (int off = 128; off > 0; off >>= 1) {
                if (tid < off) dred[tid] += dred[tid + off];
                __syncthreads();
            }
            if (tid == 0) ds[b] = dred[0];
            __syncthreads();
        }

        if (tid == 0) {
            int need = ksel - nhi;
            for (int j = 0; j < bc; j++) {
                int rank = 0;
                for (int m = 0; m < bc; m++) if (ds[m] > ds[j]) rank++;
                keptm[j] = (rank < need) ? 1 : 0;
            }
        }
        __syncthreads();

        float lsum = 0.f;
        for (int i = tid; i < N; i += 256) {
            float e = eg[i];
            if (e > e_hi) lsum += e;
        }
        if (tid == 0) {
            for (int b = 0; b < bc; b++)
                if (keptm[b]) lsum += eg[bidx[b]];
        }
        red[tid] = lsum; __syncthreads();
        for (int off = 128; off > 0; off >>= 1) {
            if (tid < off) red[tid] += red[tid + off];
            __syncthreads();
        }
        const float scale = tanhf(gmax) / (red[0] + 1e-8f);

        for (int i = tid; i < N; i += 256) {
            float e = eg[i];
            bool keep = false;
            if (e > e_hi) keep = true;
            else if (e >= e_lo) {
                for (int b = 0; b < bc; b++)
                    if (bidx[b] == i) { keep = (keptm[b] != 0); break; }
            }
            float val = keep ? e * scale : 0.f;
            orow[i] = val;
            if (keep && e > 0.f) atomicAdd(&g_colsum[cs_off + i], val);
        }
        __syncthreads();
    }
}

// ---------------- aux finish ----------------
__global__ __launch_bounds__(256) void aux_finish_kernel(
    int colsum_off, int N, float t, float* __restrict__ outscalar)
{
    int c = blockIdx.x * blockDim.x + threadIdx.x;
    float v = 0.f;
    if (c < N) {
        float m = g_colsum[colsum_off + c] * (1.0f / (float)MROWS) - t;
        v = m * m * (float)N;
    }
    __shared__ float red[256];
    red[threadIdx.x] = v; __syncthreads();
    for (int off = 128; off > 0; off >>= 1) {
        if (threadIdx.x < off) red[threadIdx.x] += red[threadIdx.x + off];
        __syncthreads();
    }
    if (threadIdx.x == 0) atomicAdd(outscalar, red[0]);
}

// ---------------- launch ----------------
extern "C" void kernel_launch(void* const* d_in, const int* in_sizes, int n_in,
                              void* d_out, int out_size) {
    const float* x      = (const float*)d_in[0];
    const float* qk     = (const float*)d_in[1];
    const float* v      = (const float*)d_in[2];
    const float* kn     = (const float*)d_in[3];
    const float* w_attn = (const float*)d_in[4];
    const float* b_attn = (const float*)d_in[5];
    const float* w_know = (const float*)d_in[6];
    const float* b_know = (const float*)d_in[7];
    float* out = (float*)d_out;

    const size_t MN  = (size_t)MROWS * NQK;
    const size_t gQ_off = 0;
    const size_t gK_off = MN;
    const size_t gV_off = 2 * MN;
    const size_t aux_attn_off = 3 * MN;
    const size_t gKn_off = aux_attn_off + 1;
    const size_t aux_know_off = gKn_off + (size_t)MROWS * NKNOW;

    static cudaStream_t s_side = nullptr;
    static cudaEvent_t evF = nullptr, evM = nullptr;
    if (s_side == nullptr) {
        cudaStreamCreateWithFlags(&s_side, cudaStreamNonBlocking);
        cudaEventCreateWithFlags(&evF, cudaEventDisableTiming);
        cudaEventCreateWithFlags(&evM, cudaEventDisableTiming);
    }

    cudaFuncSetAttribute(gemm_bf16_kernel, cudaFuncAttributeMaxDynamicSharedMemorySize, GEMM_SMEM);

    // Fork side stream FROM the captured origin stream, then zero the output
    // buffer there (hides under converts + GEMM on the main stream).
    cudaEventRecord(evF, 0);
    cudaStreamWaitEvent(s_side, evF, 0);
    cudaMemsetAsync(out, 0, (size_t)out_size * sizeof(float), s_side);
    cudaEventRecord(evM, s_side);

    init_kernel<<<(NTOT + NKNOW + 255) / 256, 256>>>();
    convertA_kernel<<<(MROWS * D_DIM / 4) / 256, 256>>>(x);
    convertB_kernel<<<(NTOT * D_DIM / 4) / 256, 256>>>(qk, v, kn);
    tau_kernel<<<MROWS, 128>>>(x, w_attn, b_attn, w_know, b_know);

    gemm_bf16_kernel<<<dim3(MROWS / 128, NTOT / 128), 256, GEMM_SMEM>>>();

    // Join: gates (sparse writers) require the memset to have completed.
    cudaStreamWaitEvent(0, evM, 0);

    gate_kernel<<<MROWS, 256>>>(0,        NQK,   64,  0, 0, out + gQ_off,  0);
    gate_kernel<<<MROWS, 256>>>(0,        NQK,   64,  1, 1, out + gK_off,  NQK);
    gate_kernel<<<MROWS, 256>>>(NQK,      NV,    64,  2, 2, out + gV_off,  2 * NQK);
    gate_kernel<<<MROWS, 256>>>(NQK + NV, NKNOW, 128, 3, 3, out + gKn_off, 3 * NQK);

    fixup_kernel<<<256, 256>>>(x, qk, v, kn,
                               out + gQ_off, out + gK_off, out + gV_off, out + gKn_off);

    aux_finish_kernel<<<NQK / 256,   256>>>(0,       NQK,   1.0f / NQK,   out + aux_attn_off);
    aux_finish_kernel<<<NQK / 256,   256>>>(NQK,     NQK,   1.0f / NQK,   out + aux_attn_off);
    aux_finish_kernel<<<NV / 256,    256>>>(2 * NQK, NV,    1.0f / NV,    out + aux_attn_off);
    aux_finish_kernel<<<NKNOW / 256, 256>>>(3 * NQK, NKNOW, 1.0f / NKNOW, out + aux_know_off);
}

// round 13
// speedup vs baseline: 1.0413x; 1.0413x over previous
#include <cuda_runtime.h>
#include <cuda_bf16.h>
#include <math.h>
#include <stdint.h>

// Problem constants (B=2, S=2048, D=1024; fixed-shape problem)
#define D_DIM   1024
#define NQK     4096
#define NV      4096
#define NKNOW   8192
#define NTOT    (NQK + NV + NKNOW)   // 16384
#define MROWS   4096                 // B*S
#define KSPLIT  3072                 // 3 x 1024 bf16-split K

#define BAND_RAW 3.1e-5f
#define THR_MIN  2e-4f
#define MAX_BAND 64
#define FIX_CAP  65536

// ---------------- scratch ----------------
__device__ float g_scores[(size_t)MROWS * NTOT];            // 268 MB
__device__ __nv_bfloat16 g_Abf[(size_t)MROWS * KSPLIT];     // 25 MB  [hi | lo | hi]
__device__ __nv_bfloat16 g_Bbf[(size_t)NTOT * KSPLIT];      // 100 MB [hi | hi | lo]
__device__ float g_tau[MROWS * 4];
__device__ float g_colsum[NTOT + NKNOW];
__device__ int   g_fix_cnt;
__device__ int   g_fix_items[FIX_CAP];

// ======================= PTX helpers (plain sm_103-safe) =======================
__device__ __forceinline__ uint32_t smem_u32(const void* p) {
    uint32_t a;
    asm("{ .reg .u64 t; cvta.to.shared.u64 t, %1; cvt.u32.u64 %0, t; }" : "=r"(a) : "l"(p));
    return a;
}
#define CP_ASYNC16(dst, src) \
    asm volatile("cp.async.cg.shared.global [%0], [%1], 16;" :: "r"(dst), "l"(src))
#define CP_COMMIT() asm volatile("cp.async.commit_group;")

__device__ __forceinline__ void ldmatrix_x4(uint32_t& r0, uint32_t& r1, uint32_t& r2, uint32_t& r3, uint32_t addr) {
    asm volatile("ldmatrix.sync.aligned.m8n8.x4.shared.b16 {%0,%1,%2,%3}, [%4];"
                 : "=r"(r0), "=r"(r1), "=r"(r2), "=r"(r3) : "r"(addr));
}
__device__ __forceinline__ void ldmatrix_x2(uint32_t& r0, uint32_t& r1, uint32_t addr) {
    asm volatile("ldmatrix.sync.aligned.m8n8.x2.shared.b16 {%0,%1}, [%2];"
                 : "=r"(r0), "=r"(r1) : "r"(addr));
}
__device__ __forceinline__ void mma_bf16(float* c, const uint32_t* a, const uint32_t* b) {
    asm volatile("mma.sync.aligned.m16n8k16.row.col.f32.bf16.bf16.f32 "
                 "{%0,%1,%2,%3}, {%4,%5,%6,%7}, {%8,%9}, {%0,%1,%2,%3};"
                 : "+f"(c[0]), "+f"(c[1]), "+f"(c[2]), "+f"(c[3])
                 : "r"(a[0]), "r"(a[1]), "r"(a[2]), "r"(a[3]), "r"(b[0]), "r"(b[1]));
}

// ---------------- init: zero colsums + fix counter + output scalars ----------------
__global__ void init_kernel(float* __restrict__ out, size_t aux_attn_off, size_t aux_know_off) {
    int i = blockIdx.x * blockDim.x + threadIdx.x;
    if (i < NTOT + NKNOW) g_colsum[i] = 0.f;
    if (i == 0) { out[aux_attn_off] = 0.f; out[aux_know_off] = 0.f; g_fix_cnt = 0; }
}

// ---------------- bf16-split conversion ----------------
__global__ __launch_bounds__(256) void convertA_kernel(const float* __restrict__ x) {
    int i = blockIdx.x * 256 + threadIdx.x;
    float4 v = ((const float4*)x)[i];
    int m = i >> 8;
    int k4 = (i & 255) << 2;
    __nv_bfloat16 h0 = __float2bfloat16(v.x), h1 = __float2bfloat16(v.y);
    __nv_bfloat16 h2 = __float2bfloat16(v.z), h3 = __float2bfloat16(v.w);
    __nv_bfloat16 l0 = __float2bfloat16(v.x - __bfloat162float(h0));
    __nv_bfloat16 l1 = __float2bfloat16(v.y - __bfloat162float(h1));
    __nv_bfloat16 l2 = __float2bfloat16(v.z - __bfloat162float(h2));
    __nv_bfloat16 l3 = __float2bfloat16(v.w - __bfloat162float(h3));
    __nv_bfloat16* base = g_Abf + (size_t)m * KSPLIT + k4;
    ((__nv_bfloat162*)(base))[0]        = __halves2bfloat162(h0, h1);
    ((__nv_bfloat162*)(base))[1]        = __halves2bfloat162(h2, h3);
    ((__nv_bfloat162*)(base + 1024))[0] = __halves2bfloat162(l0, l1);
    ((__nv_bfloat162*)(base + 1024))[1] = __halves2bfloat162(l2, l3);
    ((__nv_bfloat162*)(base + 2048))[0] = __halves2bfloat162(h0, h1);
    ((__nv_bfloat162*)(base + 2048))[1] = __halves2bfloat162(h2, h3);
}

__global__ __launch_bounds__(256) void convertB_kernel(
    const float* __restrict__ qk, const float* __restrict__ vem, const float* __restrict__ knm) {
    int i = blockIdx.x * 256 + threadIdx.x;
    int n = i >> 8;
    int k4 = (i & 255) << 2;
    const float* src;
    if (n < NQK)            src = qk  + (size_t)n * D_DIM;
    else if (n < NQK + NV)  src = vem + (size_t)(n - NQK) * D_DIM;
    else                    src = knm + (size_t)(n - NQK - NV) * D_DIM;
    float4 v = *(const float4*)(src + k4);
    __nv_bfloat16 h0 = __float2bfloat16(v.x), h1 = __float2bfloat16(v.y);
    __nv_bfloat16 h2 = __float2bfloat16(v.z), h3 = __float2bfloat16(v.w);
    __nv_bfloat16 l0 = __float2bfloat16(v.x - __bfloat162float(h0));
    __nv_bfloat16 l1 = __float2bfloat16(v.y - __bfloat162float(h1));
    __nv_bfloat16 l2 = __float2bfloat16(v.z - __bfloat162float(h2));
    __nv_bfloat16 l3 = __float2bfloat16(v.w - __bfloat162float(h3));
    __nv_bfloat16* base = g_Bbf + (size_t)n * KSPLIT + k4;
    ((__nv_bfloat162*)(base))[0]        = __halves2bfloat162(h0, h1);
    ((__nv_bfloat162*)(base))[1]        = __halves2bfloat162(h2, h3);
    ((__nv_bfloat162*)(base + 1024))[0] = __halves2bfloat162(h0, h1);
    ((__nv_bfloat162*)(base + 1024))[1] = __halves2bfloat162(h2, h3);
    ((__nv_bfloat162*)(base + 2048))[0] = __halves2bfloat162(l0, l1);
    ((__nv_bfloat162*)(base + 2048))[1] = __halves2bfloat162(l2, l3);
}

// ---------------- tau kernel ----------------
__global__ __launch_bounds__(128) void tau_kernel(
    const float* __restrict__ x,
    const float* __restrict__ w_attn, const float* __restrict__ b_attn,
    const float* __restrict__ w_know, const float* __restrict__ b_know)
{
    int r = blockIdx.x;
    const float* xr = x + (size_t)r * D_DIM;
    float s0 = 0.f, s1 = 0.f, s2 = 0.f, s3 = 0.f;
    for (int d = threadIdx.x; d < D_DIM; d += 128) {
        float xv = xr[d];
        s0 += xv * w_attn[d * 3 + 0];
        s1 += xv * w_attn[d * 3 + 1];
        s2 += xv * w_attn[d * 3 + 2];
        s3 += xv * w_know[d];
    }
    __shared__ float red[4][128];
    red[0][threadIdx.x] = s0; red[1][threadIdx.x] = s1;
    red[2][threadIdx.x] = s2; red[3][threadIdx.x] = s3;
    __syncthreads();
    for (int off = 64; off > 0; off >>= 1) {
        if (threadIdx.x < off) {
            red[0][threadIdx.x] += red[0][threadIdx.x + off];
            red[1][threadIdx.x] += red[1][threadIdx.x + off];
            red[2][threadIdx.x] += red[2][threadIdx.x + off];
            red[3][threadIdx.x] += red[3][threadIdx.x + off];
        }
        __syncthreads();
    }
    if (threadIdx.x == 0) {
        g_tau[r * 4 + 0] = red[0][0] + b_attn[0];
        g_tau[r * 4 + 1] = red[1][0] + b_attn[1];
        g_tau[r * 4 + 2] = red[2][0] + b_attn[2];
        g_tau[r * 4 + 3] = red[3][0] + b_know[0];
    }
}

// ---------------- mma.sync bf16 GEMM (exact R4 champion config) ----------------
#define STG_SZ  20480                 // A (10240) + B (10240) per stage
#define NSTAGE  3
#define KITERS  (KSPLIT / 32)         // 96
#define GEMM_SMEM (NSTAGE * STG_SZ)   // 61440

__device__ __forceinline__ void gemm_load_stage(uint32_t sbase,
    const __nv_bfloat16* gA, const __nv_bfloat16* gB, int kit, int s, int tid)
{
    const int k0 = kit * 32;
    const uint32_t st = sbase + s * STG_SZ;
#pragma unroll
    for (int i = 0; i < 2; i++) {
        int c = tid + i * 256;
        int row = c >> 2, c4 = c & 3;
        CP_ASYNC16(st + row * 80 + c4 * 16,
                   gA + (size_t)row * KSPLIT + k0 + c4 * 8);
    }
#pragma unroll
    for (int i = 0; i < 2; i++) {
        int c = tid + i * 256;
        int row = c >> 2, c4 = c & 3;
        CP_ASYNC16(st + 10240 + row * 80 + c4 * 16,
                   gB + (size_t)row * KSPLIT + k0 + c4 * 8);
    }
}

__global__ __launch_bounds__(256, 2) void gemm_bf16_kernel() {
    extern __shared__ __align__(128) char smem[];
    const uint32_t sbase = smem_u32(smem);
    const int tid = threadIdx.x;
    const int wid = tid >> 5;
    const int lid = tid & 31;
    const int m0 = blockIdx.x * 128;
    const int n0 = blockIdx.y * 128;
    const int wm = wid & 1;
    const int wn = wid >> 1;

    const __nv_bfloat16* gA = g_Abf + (size_t)m0 * KSPLIT;
    const __nv_bfloat16* gB = g_Bbf + (size_t)n0 * KSPLIT;

    const int arow = (lid & 7) + ((lid >> 3) & 1) * 8;
    const int acol = (lid >> 4) * 8;
    const int brow = lid & 7;
    const int bcol = ((lid >> 3) & 1) * 8;

    float acc[4][4][4];
#pragma unroll
    for (int i = 0; i < 4; i++)
#pragma unroll
        for (int j = 0; j < 4; j++)
#pragma unroll
            for (int q = 0; q < 4; q++) acc[i][j][q] = 0.f;

    gemm_load_stage(sbase, gA, gB, 0, 0, tid); CP_COMMIT();
    gemm_load_stage(sbase, gA, gB, 1, 1, tid); CP_COMMIT();

#pragma unroll 1
    for (int k = 0; k < KITERS; k++) {
        const int s = k % NSTAGE;
        if (k < KITERS - 2) asm volatile("cp.async.wait_group 1;");
        else                asm volatile("cp.async.wait_group 0;");
        __syncthreads();

        const uint32_t sA = sbase + s * STG_SZ;
        const uint32_t sB = sA + 10240;
#pragma unroll
        for (int ks = 0; ks < 2; ks++) {
            const int kb = ks * 16;
            uint32_t a[4][4], b[4][2];
            const uint32_t a_base = sA + (uint32_t)(wm * 64 + arow) * 80u + (uint32_t)(kb + acol) * 2u;
#pragma unroll
            for (int i = 0; i < 4; i++)
                ldmatrix_x4(a[i][0], a[i][1], a[i][2], a[i][3], a_base + (uint32_t)(i * 16 * 80));
            const uint32_t b_base = sB + (uint32_t)(wn * 32 + brow) * 80u + (uint32_t)(kb + bcol) * 2u;
#pragma unroll
            for (int j = 0; j < 4; j++)
                ldmatrix_x2(b[j][0], b[j][1], b_base + (uint32_t)(j * 8 * 80));
#pragma unroll
            for (int i = 0; i < 4; i++)
#pragma unroll
                for (int j = 0; j < 4; j++)
                    mma_bf16(acc[i][j], a[i], b[j]);
        }

        if (k + 2 < KITERS) {
            gemm_load_stage(sbase, gA, gB, k + 2, (k + 2) % NSTAGE, tid);
            CP_COMMIT();
        }
    }

    const int r4 = lid >> 2;
    const int c2 = (lid & 3) * 2;
#pragma unroll
    for (int i = 0; i < 4; i++) {
#pragma unroll
        for (int j = 0; j < 4; j++) {
            int row = m0 + wm * 64 + i * 16 + r4;
            int col = n0 + wn * 32 + j * 8 + c2;
            float* p0 = g_scores + (size_t)row * NTOT + col;
            float* p1 = g_scores + (size_t)(row + 8) * NTOT + col;
            *(float2*)p0 = make_float2(acc[i][j][0], acc[i][j][1]);
            *(float2*)p1 = make_float2(acc[i][j][2], acc[i][j][3]);
        }
    }
}

// ---------------- gate kernel (R4 logic; smem sized to N for occupancy) ----------------
template<int N, int KSEL>
__global__ __launch_bounds__(256) void gate_kernel(
    int seg_off, int tau_idx, int gate_id,
    float* __restrict__ out, int colsum_off)
{
    const int r = blockIdx.x;
    const float* s = g_scores + (size_t)r * NTOT + seg_off;
    const float tauv = g_tau[r * 4 + tau_idx];

    __shared__ float eg[N];                 // 16 KB for N=4096 -> 8 CTAs/SM
    __shared__ unsigned hist[256];
    __shared__ float red[256];
    __shared__ unsigned sh_sel;
    __shared__ int sh_kneed;
    __shared__ int sh_bandcnt;
    const int tid = threadIdx.x;

    // Pass 1: exp_gate + global max (exp(1e-8*e^raw)-1 == 0 exactly in f32 for raw<=0)
    float lmax = 0.f;
    for (int i = tid; i < N; i += 256) {
        float raw = s[i] - tauv;
        float e = (raw > 0.f) ? (expf(raw) - 1.f) : 0.f;
        eg[i] = e;
        lmax = fmaxf(lmax, e);
    }
    red[tid] = lmax; __syncthreads();
    for (int off = 128; off > 0; off >>= 1) {
        if (tid < off) red[tid] = fmaxf(red[tid], red[tid + off]);
        __syncthreads();
    }
    const float gmax = red[0];
    __syncthreads();

    // radix select: exact k-th largest (float bits order == value order, all >= 0)
    unsigned prefix = 0u, mask = 0u;
    int kneed = KSEL;
    for (int shift = 24; shift >= 0; shift -= 8) {
        hist[tid] = 0u;
        __syncthreads();
        for (int i = tid; i < N; i += 256) {
            unsigned b = __float_as_uint(eg[i]);
            if ((b & mask) == prefix) atomicAdd(&hist[(b >> shift) & 0xFFu], 1u);
        }
        __syncthreads();
        if (tid == 0) {
            unsigned cum = 0u; int sel = 0; int newk = kneed;
            for (int bin = 255; bin >= 0; bin--) {
                unsigned h = hist[bin];
                if (cum + h >= (unsigned)kneed) { sel = bin; newk = kneed - (int)cum; break; }
                cum += h;
            }
            sh_sel = (unsigned)sel; sh_kneed = newk;
        }
        __syncthreads();
        prefix |= sh_sel << shift;
        mask   |= 0xFFu << shift;
        kneed   = sh_kneed;
        __syncthreads();
    }
    const float thr = __uint_as_float(prefix);

    // Ambiguity band detection
    bool need_fix = false;
    if (thr > THR_MIN) {
        float width = (thr + 1.0f) * BAND_RAW;
        float e_hi = thr + width, e_lo = thr - width;
        if (tid == 0) sh_bandcnt = 0;
        __syncthreads();
        int c = 0;
        for (int i = tid; i < N; i += 256) {
            float e = eg[i];
            if (e >= e_lo && e <= e_hi) c++;
        }
        if (c) atomicAdd(&sh_bandcnt, c);
        __syncthreads();
        need_fix = (sh_bandcnt > 1);
    }

    if (need_fix) {
        if (tid == 0) {
            int idx = atomicAdd(&g_fix_cnt, 1);
            if (idx < FIX_CAP) g_fix_items[idx] = r | (gate_id << 16);
        }
        return;  // fixup kernel rewrites this row entirely
    }

    // Pass 2: sum of kept entries
    float lsum = 0.f;
    for (int i = tid; i < N; i += 256) {
        float e = eg[i];
        if (e >= thr) lsum += e;
    }
    red[tid] = lsum; __syncthreads();
    for (int off = 128; off > 0; off >>= 1) {
        if (tid < off) red[tid] += red[tid + off];
        __syncthreads();
    }
    const float scale = tanhf(gmax) / (red[0] + 1e-8f);

    // Pass 3: dense output + column sums
    float* orow = out + (size_t)r * N;
    for (int i = tid; i < N; i += 256) {
        float e = eg[i];
        float val = (e >= thr) ? e * scale : 0.f;
        orow[i] = val;
        if (e >= thr && e > 0.f) atomicAdd(&g_colsum[colsum_off + i], val);
    }
}

// ---------------- radix select for fixup ----------------
__device__ float radix_select_kth(const float* eg, int N, int ksel,
                                  unsigned* hist, unsigned* sh_sel, int* sh_kneed)
{
    const int tid = threadIdx.x;
    unsigned prefix = 0u, mask = 0u;
    int kneed = ksel;
    for (int shift = 24; shift >= 0; shift -= 8) {
        hist[tid] = 0u;
        __syncthreads();
        for (int i = tid; i < N; i += 256) {
            unsigned b = __float_as_uint(eg[i]);
            if ((b & mask) == prefix) atomicAdd(&hist[(b >> shift) & 0xFFu], 1u);
        }
        __syncthreads();
        if (tid == 0) {
            unsigned cum = 0u; int sel = 0; int newk = kneed;
            for (int bin = 255; bin >= 0; bin--) {
                unsigned h = hist[bin];
                if (cum + h >= (unsigned)kneed) { sel = bin; newk = kneed - (int)cum; break; }
                cum += h;
            }
            *sh_sel = (unsigned)sel; *sh_kneed = newk;
        }
        __syncthreads();
        prefix |= (*sh_sel) << shift;
        mask   |= 0xFFu << shift;
        kneed   = *sh_kneed;
        __syncthreads();
    }
    return __uint_as_float(prefix);
}

// ---------------- fixup kernel: exact fp64 re-ranking of ambiguous rows ----------------
__global__ __launch_bounds__(256) void fixup_kernel(
    const float* __restrict__ x,
    const float* __restrict__ qk, const float* __restrict__ vem, const float* __restrict__ knm,
    float* __restrict__ outQ, float* __restrict__ outK,
    float* __restrict__ outV, float* __restrict__ outKn)
{
    __shared__ float eg[NKNOW];
    __shared__ unsigned hist[256];
    __shared__ float red[256];
    __shared__ double dred[256];
    __shared__ unsigned sh_sel;
    __shared__ int sh_kneed;
    __shared__ int bidx[MAX_BAND];
    __shared__ double ds[MAX_BAND];
    __shared__ int keptm[MAX_BAND];
    __shared__ int sh_bc, sh_nhi;
    const int tid = threadIdx.x;

    int nfix = g_fix_cnt; if (nfix > FIX_CAP) nfix = FIX_CAP;

    for (int it = blockIdx.x; it < nfix; it += gridDim.x) {
        int code = g_fix_items[it];
        int r = code & 0xFFFF;
        int gate = code >> 16;

        int seg_off, N, ksel, tau_idx, cs_off;
        const float* emb; float* orow;
        if      (gate == 0) { seg_off = 0;        N = NQK;   ksel = 64;  tau_idx = 0; emb = qk;  orow = outQ;  cs_off = 0; }
        else if (gate == 1) { seg_off = 0;        N = NQK;   ksel = 64;  tau_idx = 1; emb = qk;  orow = outK;  cs_off = NQK; }
        else if (gate == 2) { seg_off = NQK;      N = NV;    ksel = 64;  tau_idx = 2; emb = vem; orow = outV;  cs_off = 2 * NQK; }
        else                { seg_off = NQK + NV; N = NKNOW; ksel = 128; tau_idx = 3; emb = knm; orow = outKn; cs_off = 3 * NQK; }
        orow += (size_t)r * N;

        const float* s = g_scores + (size_t)r * NTOT + seg_off;
        const float tauv = g_tau[r * 4 + tau_idx];

        float lmax = 0.f;
        for (int i = tid; i < N; i += 256) {
            float raw = s[i] - tauv;
            float e = (raw > 0.f) ? (expf(raw) - 1.f) : 0.f;
            eg[i] = e;
            lmax = fmaxf(lmax, e);
        }
        red[tid] = lmax; __syncthreads();
        for (int off = 128; off > 0; off >>= 1) {
            if (tid < off) red[tid] = fmaxf(red[tid], red[tid + off]);
            __syncthreads();
        }
        const float gmax = red[0];
        __syncthreads();

        const float thr = radix_select_kth(eg, N, ksel, hist, &sh_sel, &sh_kneed);
        const float width = (thr + 1.0f) * BAND_RAW;
        const float e_hi = thr + width, e_lo = thr - width;

        if (tid == 0) { sh_bc = 0; sh_nhi = 0; }
        __syncthreads();
        for (int i = tid; i < N; i += 256) {
            float e = eg[i];
            if (e > e_hi) atomicAdd(&sh_nhi, 1);
            else if (e >= e_lo) {
                int p = atomicAdd(&sh_bc, 1);
                if (p < MAX_BAND) bidx[p] = i;
            }
        }
        __syncthreads();
        const int bc = (sh_bc < MAX_BAND) ? sh_bc : MAX_BAND;
        const int nhi = sh_nhi;

        const float* xr = x + (size_t)r * D_DIM;
        for (int b = 0; b < bc; b++) {
            const float* er = emb + (size_t)bidx[b] * D_DIM;
            double part = 0.0;
            for (int d = tid; d < D_DIM; d += 256)
                part += (double)xr[d] * (double)er[d];
            dred[tid] = part; __syncthreads();
            for (int off = 128; off > 0; off >>= 1) {
                if (tid < off) dred[tid] += dred[tid + off];
                __syncthreads();
            }
            if (tid == 0) ds[b] = dred[0];
            __syncthreads();
        }

        if (tid == 0) {
            int need = ksel - nhi;
            for (int j = 0; j < bc; j++) {
                int rank = 0;
                for (int m = 0; m < bc; m++) if (ds[m] > ds[j]) rank++;
                keptm[j] = (rank < need) ? 1 : 0;
            }
        }
        __syncthreads();

        float lsum = 0.f;
        for (int i = tid; i < N; i += 256) {
            float e = eg[i];
            if (e > e_hi) lsum += e;
        }
        if (tid == 0) {
            for (int b = 0; b < bc; b++)
                if (keptm[b]) lsum += eg[bidx[b]];
        }
        red[tid] = lsum; __syncthreads();
        for (int off = 128; off > 0; off >>= 1) {
            if (tid < off) red[tid] += red[tid + off];
            __syncthreads();
        }
        const float scale = tanhf(gmax) / (red[0] + 1e-8f);

        for (int i = tid; i < N; i += 256) {
            float e = eg[i];
            bool keep = false;
            if (e > e_hi) keep = true;
            else if (e >= e_lo) {
                for (int b = 0; b < bc; b++)
                    if (bidx[b] == i) { keep = (keptm[b] != 0); break; }
            }
            float val = keep ? e * scale : 0.f;
            orow[i] = val;
            if (keep && e > 0.f) atomicAdd(&g_colsum[cs_off + i], val);
        }
        __syncthreads();
    }
}

// ---------------- aux finish ----------------
__global__ __launch_bounds__(256) void aux_finish_kernel(
    int colsum_off, int N, float t, float* __restrict__ outscalar)
{
    int c = blockIdx.x * blockDim.x + threadIdx.x;
    float v = 0.f;
    if (c < N) {
        float m = g_colsum[colsum_off + c] * (1.0f / (float)MROWS) - t;
        v = m * m * (float)N;
    }
    __shared__ float red[256];
    red[threadIdx.x] = v; __syncthreads();
    for (int off = 128; off > 0; off >>= 1) {
        if (threadIdx.x < off) red[threadIdx.x] += red[threadIdx.x + off];
        __syncthreads();
    }
    if (threadIdx.x == 0) atomicAdd(outscalar, red[0]);
}

// ---------------- launch (exact R4 structure: single stream) ----------------
extern "C" void kernel_launch(void* const* d_in, const int* in_sizes, int n_in,
                              void* d_out, int out_size) {
    const float* x      = (const float*)d_in[0];
    const float* qk     = (const float*)d_in[1];
    const float* v      = (const float*)d_in[2];
    const float* kn     = (const float*)d_in[3];
    const float* w_attn = (const float*)d_in[4];
    const float* b_attn = (const float*)d_in[5];
    const float* w_know = (const float*)d_in[6];
    const float* b_know = (const float*)d_in[7];
    float* out = (float*)d_out;

    const size_t MN  = (size_t)MROWS * NQK;
    const size_t gQ_off = 0;
    const size_t gK_off = MN;
    const size_t gV_off = 2 * MN;
    const size_t aux_attn_off = 3 * MN;
    const size_t gKn_off = aux_attn_off + 1;
    const size_t aux_know_off = gKn_off + (size_t)MROWS * NKNOW;

    cudaFuncSetAttribute(gemm_bf16_kernel, cudaFuncAttributeMaxDynamicSharedMemorySize, GEMM_SMEM);

    init_kernel<<<(NTOT + NKNOW + 255) / 256, 256>>>(out, aux_attn_off, aux_know_off);

    convertA_kernel<<<(MROWS * D_DIM / 4) / 256, 256>>>(x);
    convertB_kernel<<<(NTOT * D_DIM / 4) / 256, 256>>>(qk, v, kn);

    tau_kernel<<<MROWS, 128>>>(x, w_attn, b_attn, w_know, b_know);

    gemm_bf16_kernel<<<dim3(MROWS / 128, NTOT / 128), 256, GEMM_SMEM>>>();

    gate_kernel<NQK,   64 ><<<MROWS, 256>>>(0,        0, 0, out + gQ_off,  0);
    gate_kernel<NQK,   64 ><<<MROWS, 256>>>(0,        1, 1, out + gK_off,  NQK);
    gate_kernel<NV,    64 ><<<MROWS, 256>>>(NQK,      2, 2, out + gV_off,  2 * NQK);
    gate_kernel<NKNOW, 128><<<MROWS, 256>>>(NQK + NV, 3, 3, out + gKn_off, 3 * NQK);

    fixup_kernel<<<256, 256>>>(x, qk, v, kn,
                               out + gQ_off, out + gK_off, out + gV_off, out + gKn_off);

    aux_finish_kernel<<<NQK / 256,   256>>>(0,       NQK,   1.0f / NQK,   out + aux_attn_off);
    aux_finish_kernel<<<NQK / 256,   256>>>(NQK,     NQK,   1.0f / NQK,   out + aux_attn_off);
    aux_finish_kernel<<<NV / 256,    256>>>(2 * NQK, NV,    1.0f / NV,    out + aux_attn_off);
    aux_finish_kernel<<<NKNOW / 256, 256>>>(3 * NQK, NKNOW, 1.0f / NKNOW, out + aux_know_off);
}

// round 14
// speedup vs baseline: 1.0448x; 1.0034x over previous
#include <cuda_runtime.h>
#include <cuda_bf16.h>
#include <math.h>
#include <stdint.h>

// Problem constants (B=2, S=2048, D=1024; fixed-shape problem)
#define D_DIM   1024
#define NQK     4096
#define NV      4096
#define NKNOW   8192
#define NTOT    (NQK + NV + NKNOW)   // 16384
#define MROWS   4096                 // B*S
#define KSPLIT  3072                 // 3 x 1024 bf16-split K

#define BAND_RAW 3.1e-5f
#define THR_MIN  2e-4f
#define MAX_BAND 64
#define FIX_CAP  65536

// fast exp gate: exp(raw)-1 for raw>0 else 0.
// __expf (MUFU.EX2 path) differs from expf by <~5e-7 rel; threshold-crossing
// discrepancies fall inside the BAND_RAW ambiguity band -> fp64 fixup.
__device__ __forceinline__ float egate(float raw) {
    return (raw > 0.f) ? (__expf(raw) - 1.f) : 0.f;
}

// ---------------- scratch ----------------
__device__ float g_scores[(size_t)MROWS * NTOT];            // 268 MB
__device__ __nv_bfloat16 g_Abf[(size_t)MROWS * KSPLIT];     // 25 MB  [hi | lo | hi]
__device__ __nv_bfloat16 g_Bbf[(size_t)NTOT * KSPLIT];      // 100 MB [hi | hi | lo]
__device__ float g_tau[MROWS * 4];
__device__ float g_colsum[NTOT + NKNOW];
__device__ int   g_fix_cnt;
__device__ int   g_fix_items[FIX_CAP];

// ======================= PTX helpers (plain sm_103-safe) =======================
__device__ __forceinline__ uint32_t smem_u32(const void* p) {
    uint32_t a;
    asm("{ .reg .u64 t; cvta.to.shared.u64 t, %1; cvt.u32.u64 %0, t; }" : "=r"(a) : "l"(p));
    return a;
}
#define CP_ASYNC16(dst, src) \
    asm volatile("cp.async.cg.shared.global [%0], [%1], 16;" :: "r"(dst), "l"(src))
#define CP_COMMIT() asm volatile("cp.async.commit_group;")

__device__ __forceinline__ void ldmatrix_x4(uint32_t& r0, uint32_t& r1, uint32_t& r2, uint32_t& r3, uint32_t addr) {
    asm volatile("ldmatrix.sync.aligned.m8n8.x4.shared.b16 {%0,%1,%2,%3}, [%4];"
                 : "=r"(r0), "=r"(r1), "=r"(r2), "=r"(r3) : "r"(addr));
}
__device__ __forceinline__ void ldmatrix_x2(uint32_t& r0, uint32_t& r1, uint32_t addr) {
    asm volatile("ldmatrix.sync.aligned.m8n8.x2.shared.b16 {%0,%1}, [%2];"
                 : "=r"(r0), "=r"(r1) : "r"(addr));
}
__device__ __forceinline__ void mma_bf16(float* c, const uint32_t* a, const uint32_t* b) {
    asm volatile("mma.sync.aligned.m16n8k16.row.col.f32.bf16.bf16.f32 "
                 "{%0,%1,%2,%3}, {%4,%5,%6,%7}, {%8,%9}, {%0,%1,%2,%3};"
                 : "+f"(c[0]), "+f"(c[1]), "+f"(c[2]), "+f"(c[3])
                 : "r"(a[0]), "r"(a[1]), "r"(a[2]), "r"(a[3]), "r"(b[0]), "r"(b[1]));
}

// ---------------- init: zero colsums + fix counter + output scalars ----------------
__global__ void init_kernel(float* __restrict__ out, size_t aux_attn_off, size_t aux_know_off) {
    int i = blockIdx.x * blockDim.x + threadIdx.x;
    if (i < NTOT + NKNOW) g_colsum[i] = 0.f;
    if (i == 0) { out[aux_attn_off] = 0.f; out[aux_know_off] = 0.f; g_fix_cnt = 0; }
}

// ---------------- bf16-split conversion ----------------
__global__ __launch_bounds__(256) void convertA_kernel(const float* __restrict__ x) {
    int i = blockIdx.x * 256 + threadIdx.x;
    float4 v = ((const float4*)x)[i];
    int m = i >> 8;
    int k4 = (i & 255) << 2;
    __nv_bfloat16 h0 = __float2bfloat16(v.x), h1 = __float2bfloat16(v.y);
    __nv_bfloat16 h2 = __float2bfloat16(v.z), h3 = __float2bfloat16(v.w);
    __nv_bfloat16 l0 = __float2bfloat16(v.x - __bfloat162float(h0));
    __nv_bfloat16 l1 = __float2bfloat16(v.y - __bfloat162float(h1));
    __nv_bfloat16 l2 = __float2bfloat16(v.z - __bfloat162float(h2));
    __nv_bfloat16 l3 = __float2bfloat16(v.w - __bfloat162float(h3));
    __nv_bfloat16* base = g_Abf + (size_t)m * KSPLIT + k4;
    ((__nv_bfloat162*)(base))[0]        = __halves2bfloat162(h0, h1);
    ((__nv_bfloat162*)(base))[1]        = __halves2bfloat162(h2, h3);
    ((__nv_bfloat162*)(base + 1024))[0] = __halves2bfloat162(l0, l1);
    ((__nv_bfloat162*)(base + 1024))[1] = __halves2bfloat162(l2, l3);
    ((__nv_bfloat162*)(base + 2048))[0] = __halves2bfloat162(h0, h1);
    ((__nv_bfloat162*)(base + 2048))[1] = __halves2bfloat162(h2, h3);
}

__global__ __launch_bounds__(256) void convertB_kernel(
    const float* __restrict__ qk, const float* __restrict__ vem, const float* __restrict__ knm) {
    int i = blockIdx.x * 256 + threadIdx.x;
    int n = i >> 8;
    int k4 = (i & 255) << 2;
    const float* src;
    if (n < NQK)            src = qk  + (size_t)n * D_DIM;
    else if (n < NQK + NV)  src = vem + (size_t)(n - NQK) * D_DIM;
    else                    src = knm + (size_t)(n - NQK - NV) * D_DIM;
    float4 v = *(const float4*)(src + k4);
    __nv_bfloat16 h0 = __float2bfloat16(v.x), h1 = __float2bfloat16(v.y);
    __nv_bfloat16 h2 = __float2bfloat16(v.z), h3 = __float2bfloat16(v.w);
    __nv_bfloat16 l0 = __float2bfloat16(v.x - __bfloat162float(h0));
    __nv_bfloat16 l1 = __float2bfloat16(v.y - __bfloat162float(h1));
    __nv_bfloat16 l2 = __float2bfloat16(v.z - __bfloat162float(h2));
    __nv_bfloat16 l3 = __float2bfloat16(v.w - __bfloat162float(h3));
    __nv_bfloat16* base = g_Bbf + (size_t)n * KSPLIT + k4;
    ((__nv_bfloat162*)(base))[0]        = __halves2bfloat162(h0, h1);
    ((__nv_bfloat162*)(base))[1]        = __halves2bfloat162(h2, h3);
    ((__nv_bfloat162*)(base + 1024))[0] = __halves2bfloat162(h0, h1);
    ((__nv_bfloat162*)(base + 1024))[1] = __halves2bfloat162(h2, h3);
    ((__nv_bfloat162*)(base + 2048))[0] = __halves2bfloat162(l0, l1);
    ((__nv_bfloat162*)(base + 2048))[1] = __halves2bfloat162(l2, l3);
}

// ---------------- tau kernel ----------------
__global__ __launch_bounds__(128) void tau_kernel(
    const float* __restrict__ x,
    const float* __restrict__ w_attn, const float* __restrict__ b_attn,
    const float* __restrict__ w_know, const float* __restrict__ b_know)
{
    int r = blockIdx.x;
    const float* xr = x + (size_t)r * D_DIM;
    float s0 = 0.f, s1 = 0.f, s2 = 0.f, s3 = 0.f;
    for (int d = threadIdx.x; d < D_DIM; d += 128) {
        float xv = xr[d];
        s0 += xv * w_attn[d * 3 + 0];
        s1 += xv * w_attn[d * 3 + 1];
        s2 += xv * w_attn[d * 3 + 2];
        s3 += xv * w_know[d];
    }
    __shared__ float red[4][128];
    red[0][threadIdx.x] = s0; red[1][threadIdx.x] = s1;
    red[2][threadIdx.x] = s2; red[3][threadIdx.x] = s3;
    __syncthreads();
    for (int off = 64; off > 0; off >>= 1) {
        if (threadIdx.x < off) {
            red[0][threadIdx.x] += red[0][threadIdx.x + off];
            red[1][threadIdx.x] += red[1][threadIdx.x + off];
            red[2][threadIdx.x] += red[2][threadIdx.x + off];
            red[3][threadIdx.x] += red[3][threadIdx.x + off];
        }
        __syncthreads();
    }
    if (threadIdx.x == 0) {
        g_tau[r * 4 + 0] = red[0][0] + b_attn[0];
        g_tau[r * 4 + 1] = red[1][0] + b_attn[1];
        g_tau[r * 4 + 2] = red[2][0] + b_attn[2];
        g_tau[r * 4 + 3] = red[3][0] + b_know[0];
    }
}

// ---------------- mma.sync bf16 GEMM (exact R4 champion config) ----------------
#define STG_SZ  20480                 // A (10240) + B (10240) per stage
#define NSTAGE  3
#define KITERS  (KSPLIT / 32)         // 96
#define GEMM_SMEM (NSTAGE * STG_SZ)   // 61440

__device__ __forceinline__ void gemm_load_stage(uint32_t sbase,
    const __nv_bfloat16* gA, const __nv_bfloat16* gB, int kit, int s, int tid)
{
    const int k0 = kit * 32;
    const uint32_t st = sbase + s * STG_SZ;
#pragma unroll
    for (int i = 0; i < 2; i++) {
        int c = tid + i * 256;
        int row = c >> 2, c4 = c & 3;
        CP_ASYNC16(st + row * 80 + c4 * 16,
                   gA + (size_t)row * KSPLIT + k0 + c4 * 8);
    }
#pragma unroll
    for (int i = 0; i < 2; i++) {
        int c = tid + i * 256;
        int row = c >> 2, c4 = c & 3;
        CP_ASYNC16(st + 10240 + row * 80 + c4 * 16,
                   gB + (size_t)row * KSPLIT + k0 + c4 * 8);
    }
}

__global__ __launch_bounds__(256, 2) void gemm_bf16_kernel() {
    extern __shared__ __align__(128) char smem[];
    const uint32_t sbase = smem_u32(smem);
    const int tid = threadIdx.x;
    const int wid = tid >> 5;
    const int lid = tid & 31;
    const int m0 = blockIdx.x * 128;
    const int n0 = blockIdx.y * 128;
    const int wm = wid & 1;
    const int wn = wid >> 1;

    const __nv_bfloat16* gA = g_Abf + (size_t)m0 * KSPLIT;
    const __nv_bfloat16* gB = g_Bbf + (size_t)n0 * KSPLIT;

    const int arow = (lid & 7) + ((lid >> 3) & 1) * 8;
    const int acol = (lid >> 4) * 8;
    const int brow = lid & 7;
    const int bcol = ((lid >> 3) & 1) * 8;

    float acc[4][4][4];
#pragma unroll
    for (int i = 0; i < 4; i++)
#pragma unroll
        for (int j = 0; j < 4; j++)
#pragma unroll
            for (int q = 0; q < 4; q++) acc[i][j][q] = 0.f;

    gemm_load_stage(sbase, gA, gB, 0, 0, tid); CP_COMMIT();
    gemm_load_stage(sbase, gA, gB, 1, 1, tid); CP_COMMIT();

#pragma unroll 1
    for (int k = 0; k < KITERS; k++) {
        const int s = k % NSTAGE;
        if (k < KITERS - 2) asm volatile("cp.async.wait_group 1;");
        else                asm volatile("cp.async.wait_group 0;");
        __syncthreads();

        const uint32_t sA = sbase + s * STG_SZ;
        const uint32_t sB = sA + 10240;
#pragma unroll
        for (int ks = 0; ks < 2; ks++) {
            const int kb = ks * 16;
            uint32_t a[4][4], b[4][2];
            const uint32_t a_base = sA + (uint32_t)(wm * 64 + arow) * 80u + (uint32_t)(kb + acol) * 2u;
#pragma unroll
            for (int i = 0; i < 4; i++)
                ldmatrix_x4(a[i][0], a[i][1], a[i][2], a[i][3], a_base + (uint32_t)(i * 16 * 80));
            const uint32_t b_base = sB + (uint32_t)(wn * 32 + brow) * 80u + (uint32_t)(kb + bcol) * 2u;
#pragma unroll
            for (int j = 0; j < 4; j++)
                ldmatrix_x2(b[j][0], b[j][1], b_base + (uint32_t)(j * 8 * 80));
#pragma unroll
            for (int i = 0; i < 4; i++)
#pragma unroll
                for (int j = 0; j < 4; j++)
                    mma_bf16(acc[i][j], a[i], b[j]);
        }

        if (k + 2 < KITERS) {
            gemm_load_stage(sbase, gA, gB, k + 2, (k + 2) % NSTAGE, tid);
            CP_COMMIT();
        }
    }

    const int r4 = lid >> 2;
    const int c2 = (lid & 3) * 2;
#pragma unroll
    for (int i = 0; i < 4; i++) {
#pragma unroll
        for (int j = 0; j < 4; j++) {
            int row = m0 + wm * 64 + i * 16 + r4;
            int col = n0 + wn * 32 + j * 8 + c2;
            float* p0 = g_scores + (size_t)row * NTOT + col;
            float* p1 = g_scores + (size_t)(row + 8) * NTOT + col;
            *(float2*)p0 = make_float2(acc[i][j][0], acc[i][j][1]);
            *(float2*)p1 = make_float2(acc[i][j][2], acc[i][j][3]);
        }
    }
}

// ---------------- gate kernel (champion logic; __expf fast path) ----------------
template<int N, int KSEL>
__global__ __launch_bounds__(256) void gate_kernel(
    int seg_off, int tau_idx, int gate_id,
    float* __restrict__ out, int colsum_off)
{
    const int r = blockIdx.x;
    const float* s = g_scores + (size_t)r * NTOT + seg_off;
    const float tauv = g_tau[r * 4 + tau_idx];

    __shared__ float eg[N];
    __shared__ unsigned hist[256];
    __shared__ float red[256];
    __shared__ unsigned sh_sel;
    __shared__ int sh_kneed;
    __shared__ int sh_bandcnt;
    const int tid = threadIdx.x;

    // Pass 1: exp_gate + global max
    float lmax = 0.f;
    for (int i = tid; i < N; i += 256) {
        float e = egate(s[i] - tauv);
        eg[i] = e;
        lmax = fmaxf(lmax, e);
    }
    red[tid] = lmax; __syncthreads();
    for (int off = 128; off > 0; off >>= 1) {
        if (tid < off) red[tid] = fmaxf(red[tid], red[tid + off]);
        __syncthreads();
    }
    const float gmax = red[0];
    __syncthreads();

    // radix select: exact k-th largest (float bits order == value order, all >= 0)
    unsigned prefix = 0u, mask = 0u;
    int kneed = KSEL;
    for (int shift = 24; shift >= 0; shift -= 8) {
        hist[tid] = 0u;
        __syncthreads();
        for (int i = tid; i < N; i += 256) {
            unsigned b = __float_as_uint(eg[i]);
            if ((b & mask) == prefix) atomicAdd(&hist[(b >> shift) & 0xFFu], 1u);
        }
        __syncthreads();
        if (tid == 0) {
            unsigned cum = 0u; int sel = 0; int newk = kneed;
            for (int bin = 255; bin >= 0; bin--) {
                unsigned h = hist[bin];
                if (cum + h >= (unsigned)kneed) { sel = bin; newk = kneed - (int)cum; break; }
                cum += h;
            }
            sh_sel = (unsigned)sel; sh_kneed = newk;
        }
        __syncthreads();
        prefix |= sh_sel << shift;
        mask   |= 0xFFu << shift;
        kneed   = sh_kneed;
        __syncthreads();
    }
    const float thr = __uint_as_float(prefix);

    // Ambiguity band detection
    bool need_fix = false;
    if (thr > THR_MIN) {
        float width = (thr + 1.0f) * BAND_RAW;
        float e_hi = thr + width, e_lo = thr - width;
        if (tid == 0) sh_bandcnt = 0;
        __syncthreads();
        int c = 0;
        for (int i = tid; i < N; i += 256) {
            float e = eg[i];
            if (e >= e_lo && e <= e_hi) c++;
        }
        if (c) atomicAdd(&sh_bandcnt, c);
        __syncthreads();
        need_fix = (sh_bandcnt > 1);
    }

    if (need_fix) {
        if (tid == 0) {
            int idx = atomicAdd(&g_fix_cnt, 1);
            if (idx < FIX_CAP) g_fix_items[idx] = r | (gate_id << 16);
        }
        return;  // fixup kernel rewrites this row entirely
    }

    // Pass 2: sum of kept entries
    float lsum = 0.f;
    for (int i = tid; i < N; i += 256) {
        float e = eg[i];
        if (e >= thr) lsum += e;
    }
    red[tid] = lsum; __syncthreads();
    for (int off = 128; off > 0; off >>= 1) {
        if (tid < off) red[tid] += red[tid + off];
        __syncthreads();
    }
    const float scale = __tanhf(gmax) / (red[0] + 1e-8f);

    // Pass 3: dense output + column sums
    float* orow = out + (size_t)r * N;
    for (int i = tid; i < N; i += 256) {
        float e = eg[i];
        float val = (e >= thr) ? e * scale : 0.f;
        orow[i] = val;
        if (e >= thr && e > 0.f) atomicAdd(&g_colsum[colsum_off + i], val);
    }
}

// ---------------- radix select for fixup ----------------
__device__ float radix_select_kth(const float* eg, int N, int ksel,
                                  unsigned* hist, unsigned* sh_sel, int* sh_kneed)
{
    const int tid = threadIdx.x;
    unsigned prefix = 0u, mask = 0u;
    int kneed = ksel;
    for (int shift = 24; shift >= 0; shift -= 8) {
        hist[tid] = 0u;
        __syncthreads();
        for (int i = tid; i < N; i += 256) {
            unsigned b = __float_as_uint(eg[i]);
            if ((b & mask) == prefix) atomicAdd(&hist[(b >> shift) & 0xFFu], 1u);
        }
        __syncthreads();
        if (tid == 0) {
            unsigned cum = 0u; int sel = 0; int newk = kneed;
            for (int bin = 255; bin >= 0; bin--) {
                unsigned h = hist[bin];
                if (cum + h >= (unsigned)kneed) { sel = bin; newk = kneed - (int)cum; break; }
                cum += h;
            }
            *sh_sel = (unsigned)sel; *sh_kneed = newk;
        }
        __syncthreads();
        prefix |= (*sh_sel) << shift;
        mask   |= 0xFFu << shift;
        kneed   = *sh_kneed;
        __syncthreads();
    }
    return __uint_as_float(prefix);
}

// ---------------- fixup kernel: exact fp64 re-ranking of ambiguous rows ----------------
__global__ __launch_bounds__(256) void fixup_kernel(
    const float* __restrict__ x,
    const float* __restrict__ qk, const float* __restrict__ vem, const float* __restrict__ knm,
    float* __restrict__ outQ, float* __restrict__ outK,
    float* __restrict__ outV, float* __restrict__ outKn)
{
    __shared__ float eg[NKNOW];
    __shared__ unsigned hist[256];
    __shared__ float red[256];
    __shared__ double dred[256];
    __shared__ unsigned sh_sel;
    __shared__ int sh_kneed;
    __shared__ int bidx[MAX_BAND];
    __shared__ double ds[MAX_BAND];
    __shared__ int keptm[MAX_BAND];
    __shared__ int sh_bc, sh_nhi;
    const int tid = threadIdx.x;

    int nfix = g_fix_cnt; if (nfix > FIX_CAP) nfix = FIX_CAP;

    for (int it = blockIdx.x; it < nfix; it += gridDim.x) {
        int code = g_fix_items[it];
        int r = code & 0xFFFF;
        int gate = code >> 16;

        int seg_off, N, ksel, tau_idx, cs_off;
        const float* emb; float* orow;
        if      (gate == 0) { seg_off = 0;        N = NQK;   ksel = 64;  tau_idx = 0; emb = qk;  orow = outQ;  cs_off = 0; }
        else if (gate == 1) { seg_off = 0;        N = NQK;   ksel = 64;  tau_idx = 1; emb = qk;  orow = outK;  cs_off = NQK; }
        else if (gate == 2) { seg_off = NQK;      N = NV;    ksel = 64;  tau_idx = 2; emb = vem; orow = outV;  cs_off = 2 * NQK; }
        else                { seg_off = NQK + NV; N = NKNOW; ksel = 128; tau_idx = 3; emb = knm; orow = outKn; cs_off = 3 * NQK; }
        orow += (size_t)r * N;

        const float* s = g_scores + (size_t)r * NTOT + seg_off;
        const float tauv = g_tau[r * 4 + tau_idx];

        float lmax = 0.f;
        for (int i = tid; i < N; i += 256) {
            float e = egate(s[i] - tauv);
            eg[i] = e;
            lmax = fmaxf(lmax, e);
        }
        red[tid] = lmax; __syncthreads();
        for (int off = 128; off > 0; off >>= 1) {
            if (tid < off) red[tid] = fmaxf(red[tid], red[tid + off]);
            __syncthreads();
        }
        const float gmax = red[0];
        __syncthreads();

        const float thr = radix_select_kth(eg, N, ksel, hist, &sh_sel, &sh_kneed);
        const float width = (thr + 1.0f) * BAND_RAW;
        const float e_hi = thr + width, e_lo = thr - width;

        if (tid == 0) { sh_bc = 0; sh_nhi = 0; }
        __syncthreads();
        for (int i = tid; i < N; i += 256) {
            float e = eg[i];
            if (e > e_hi) atomicAdd(&sh_nhi, 1);
            else if (e >= e_lo) {
                int p = atomicAdd(&sh_bc, 1);
                if (p < MAX_BAND) bidx[p] = i;
            }
        }
        __syncthreads();
        const int bc = (sh_bc < MAX_BAND) ? sh_bc : MAX_BAND;
        const int nhi = sh_nhi;

        const float* xr = x + (size_t)r * D_DIM;
        for (int b = 0; b < bc; b++) {
            const float* er = emb + (size_t)bidx[b] * D_DIM;
            double part = 0.0;
            for (int d = tid; d < D_DIM; d += 256)
                part += (double)xr[d] * (double)er[d];
            dred[tid] = part; __syncthreads();
            for (int off = 128; off > 0; off >>= 1) {
                if (tid < off) dred[tid] += dred[tid + off];
                __syncthreads();
            }
            if (tid == 0) ds[b] = dred[0];
            __syncthreads();
        }

        if (tid == 0) {
            int need = ksel - nhi;
            for (int j = 0; j < bc; j++) {
                int rank = 0;
                for (int m = 0; m < bc; m++) if (ds[m] > ds[j]) rank++;
                keptm[j] = (rank < need) ? 1 : 0;
            }
        }
        __syncthreads();

        float lsum = 0.f;
        for (int i = tid; i < N; i += 256) {
            float e = eg[i];
            if (e > e_hi) lsum += e;
        }
        if (tid == 0) {
            for (int b = 0; b < bc; b++)
                if (keptm[b]) lsum += eg[bidx[b]];
        }
        red[tid] = lsum; __syncthreads();
        for (int off = 128; off > 0; off >>= 1) {
            if (tid < off) red[tid] += red[tid + off];
            __syncthreads();
        }
        const float scale = __tanhf(gmax) / (red[0] + 1e-8f);

        for (int i = tid; i < N; i += 256) {
            float e = eg[i];
            bool keep = false;
            if (e > e_hi) keep = true;
            else if (e >= e_lo) {
                for (int b = 0; b < bc; b++)
                    if (bidx[b] == i) { keep = (keptm[b] != 0); break; }
            }
            float val = keep ? e * scale : 0.f;
            orow[i] = val;
            if (keep && e > 0.f) atomicAdd(&g_colsum[cs_off + i], val);
        }
        __syncthreads();
    }
}

// ---------------- aux finish ----------------
__global__ __launch_bounds__(256) void aux_finish_kernel(
    int colsum_off, int N, float t, float* __restrict__ outscalar)
{
    int c = blockIdx.x * blockDim.x + threadIdx.x;
    float v = 0.f;
    if (c < N) {
        float m = g_colsum[colsum_off + c] * (1.0f / (float)MROWS) - t;
        v = m * m * (float)N;
    }
    __shared__ float red[256];
    red[threadIdx.x] = v; __syncthreads();
    for (int off = 128; off > 0; off >>= 1) {
        if (threadIdx.x < off) red[threadIdx.x] += red[threadIdx.x + off];
        __syncthreads();
    }
    if (threadIdx.x == 0) atomicAdd(outscalar, red[0]);
}

// ---------------- launch (exact champion structure: single stream) ----------------
extern "C" void kernel_launch(void* const* d_in, const int* in_sizes, int n_in,
                              void* d_out, int out_size) {
    const float* x      = (const float*)d_in[0];
    const float* qk     = (const float*)d_in[1];
    const float* v      = (const float*)d_in[2];
    const float* kn     = (const float*)d_in[3];
    const float* w_attn = (const float*)d_in[4];
    const float* b_attn = (const float*)d_in[5];
    const float* w_know = (const float*)d_in[6];
    const float* b_know = (const float*)d_in[7];
    float* out = (float*)d_out;

    const size_t MN  = (size_t)MROWS * NQK;
    const size_t gQ_off = 0;
    const size_t gK_off = MN;
    const size_t gV_off = 2 * MN;
    const size_t aux_attn_off = 3 * MN;
    const size_t gKn_off = aux_attn_off + 1;
    const size_t aux_know_off = gKn_off + (size_t)MROWS * NKNOW;

    cudaFuncSetAttribute(gemm_bf16_kernel, cudaFuncAttributeMaxDynamicSharedMemorySize, GEMM_SMEM);

    init_kernel<<<(NTOT + NKNOW + 255) / 256, 256>>>(out, aux_attn_off, aux_know_off);

    convertA_kernel<<<(MROWS * D_DIM / 4) / 256, 256>>>(x);
    convertB_kernel<<<(NTOT * D_DIM / 4) / 256, 256>>>(qk, v, kn);

    tau_kernel<<<MROWS, 128>>>(x, w_attn, b_attn, w_know, b_know);

    gemm_bf16_kernel<<<dim3(MROWS / 128, NTOT / 128), 256, GEMM_SMEM>>>();

    gate_kernel<NQK,   64 ><<<MROWS, 256>>>(0,        0, 0, out + gQ_off,  0);
    gate_kernel<NQK,   64 ><<<MROWS, 256>>>(0,        1, 1, out + gK_off,  NQK);
    gate_kernel<NV,    64 ><<<MROWS, 256>>>(NQK,      2, 2, out + gV_off,  2 * NQK);
    gate_kernel<NKNOW, 128><<<MROWS, 256>>>(NQK + NV, 3, 3, out + gKn_off, 3 * NQK);

    fixup_kernel<<<256, 256>>>(x, qk, v, kn,
                               out + gQ_off, out + gK_off, out + gV_off, out + gKn_off);

    aux_finish_kernel<<<NQK / 256,   256>>>(0,       NQK,   1.0f / NQK,   out + aux_attn_off);
    aux_finish_kernel<<<NQK / 256,   256>>>(NQK,     NQK,   1.0f / NQK,   out + aux_attn_off);
    aux_finish_kernel<<<NV / 256,    256>>>(2 * NQK, NV,    1.0f / NV,    out + aux_attn_off);
    aux_finish_kernel<<<NKNOW / 256, 256>>>(3 * NQK, NKNOW, 1.0f / NKNOW, out + aux_know_off);
}

// round 15
// speedup vs baseline: 1.1946x; 1.1433x over previous
#include <cuda_runtime.h>
#include <cuda_bf16.h>
#include <math.h>
#include <stdint.h>

// Problem constants (B=2, S=2048, D=1024; fixed-shape problem)
#define D_DIM   1024
#define NQK     4096
#define NV      4096
#define NKNOW   8192
#define NTOT    (NQK + NV + NKNOW)   // 16384
#define MROWS   4096                 // B*S
#define KSPLIT  3072                 // 3 x 1024 bf16-split K

#define BAND_RAW 3.1e-5f
#define THR_MIN  2e-4f
#define MAX_BAND 64
#define FIX_CAP  65536

// fast exp gate: exp(raw)-1 for raw>0 else 0 (MUFU path; discrepancies land in band -> fixup)
__device__ __forceinline__ float egate(float raw) {
    return (raw > 0.f) ? (__expf(raw) - 1.f) : 0.f;
}

// ---------------- scratch ----------------
__device__ float g_scores[(size_t)MROWS * NTOT];            // 268 MB
__device__ __nv_bfloat16 g_Abf[(size_t)MROWS * KSPLIT];     // 25 MB  [hi | lo | hi]
__device__ __nv_bfloat16 g_Bbf[(size_t)NTOT * KSPLIT];      // 100 MB [hi | hi | lo]
__device__ float g_tau[MROWS * 4];
__device__ float g_colsum[NTOT + NKNOW];
__device__ int   g_fix_cnt;
__device__ int   g_fix_items[FIX_CAP];

// ======================= PTX helpers (plain sm_103-safe) =======================
__device__ __forceinline__ uint32_t smem_u32(const void* p) {
    uint32_t a;
    asm("{ .reg .u64 t; cvta.to.shared.u64 t, %1; cvt.u32.u64 %0, t; }" : "=r"(a) : "l"(p));
    return a;
}
#define CP_ASYNC16(dst, src) \
    asm volatile("cp.async.cg.shared.global [%0], [%1], 16;" :: "r"(dst), "l"(src))
#define CP_COMMIT() asm volatile("cp.async.commit_group;")

__device__ __forceinline__ void ldmatrix_x4(uint32_t& r0, uint32_t& r1, uint32_t& r2, uint32_t& r3, uint32_t addr) {
    asm volatile("ldmatrix.sync.aligned.m8n8.x4.shared.b16 {%0,%1,%2,%3}, [%4];"
                 : "=r"(r0), "=r"(r1), "=r"(r2), "=r"(r3) : "r"(addr));
}
__device__ __forceinline__ void ldmatrix_x2(uint32_t& r0, uint32_t& r1, uint32_t addr) {
    asm volatile("ldmatrix.sync.aligned.m8n8.x2.shared.b16 {%0,%1}, [%2];"
                 : "=r"(r0), "=r"(r1) : "r"(addr));
}
__device__ __forceinline__ void mma_bf16(float* c, const uint32_t* a, const uint32_t* b) {
    asm volatile("mma.sync.aligned.m16n8k16.row.col.f32.bf16.bf16.f32 "
                 "{%0,%1,%2,%3}, {%4,%5,%6,%7}, {%8,%9}, {%0,%1,%2,%3};"
                 : "+f"(c[0]), "+f"(c[1]), "+f"(c[2]), "+f"(c[3])
                 : "r"(a[0]), "r"(a[1]), "r"(a[2]), "r"(a[3]), "r"(b[0]), "r"(b[1]));
}

// ---------------- init: zero colsums + fix counter + output scalars ----------------
__global__ void init_kernel(float* __restrict__ out, size_t aux_attn_off, size_t aux_know_off) {
    int i = blockIdx.x * blockDim.x + threadIdx.x;
    if (i < NTOT + NKNOW) g_colsum[i] = 0.f;
    if (i == 0) { out[aux_attn_off] = 0.f; out[aux_know_off] = 0.f; g_fix_cnt = 0; }
}

// ---------------- bf16-split conversion ----------------
__global__ __launch_bounds__(256) void convertA_kernel(const float* __restrict__ x) {
    int i = blockIdx.x * 256 + threadIdx.x;
    float4 v = ((const float4*)x)[i];
    int m = i >> 8;
    int k4 = (i & 255) << 2;
    __nv_bfloat16 h0 = __float2bfloat16(v.x), h1 = __float2bfloat16(v.y);
    __nv_bfloat16 h2 = __float2bfloat16(v.z), h3 = __float2bfloat16(v.w);
    __nv_bfloat16 l0 = __float2bfloat16(v.x - __bfloat162float(h0));
    __nv_bfloat16 l1 = __float2bfloat16(v.y - __bfloat162float(h1));
    __nv_bfloat16 l2 = __float2bfloat16(v.z - __bfloat162float(h2));
    __nv_bfloat16 l3 = __float2bfloat16(v.w - __bfloat162float(h3));
    __nv_bfloat16* base = g_Abf + (size_t)m * KSPLIT + k4;
    ((__nv_bfloat162*)(base))[0]        = __halves2bfloat162(h0, h1);
    ((__nv_bfloat162*)(base))[1]        = __halves2bfloat162(h2, h3);
    ((__nv_bfloat162*)(base + 1024))[0] = __halves2bfloat162(l0, l1);
    ((__nv_bfloat162*)(base + 1024))[1] = __halves2bfloat162(l2, l3);
    ((__nv_bfloat162*)(base + 2048))[0] = __halves2bfloat162(h0, h1);
    ((__nv_bfloat162*)(base + 2048))[1] = __halves2bfloat162(h2, h3);
}

__global__ __launch_bounds__(256) void convertB_kernel(
    const float* __restrict__ qk, const float* __restrict__ vem, const float* __restrict__ knm) {
    int i = blockIdx.x * 256 + threadIdx.x;
    int n = i >> 8;
    int k4 = (i & 255) << 2;
    const float* src;
    if (n < NQK)            src = qk  + (size_t)n * D_DIM;
    else if (n < NQK + NV)  src = vem + (size_t)(n - NQK) * D_DIM;
    else                    src = knm + (size_t)(n - NQK - NV) * D_DIM;
    float4 v = *(const float4*)(src + k4);
    __nv_bfloat16 h0 = __float2bfloat16(v.x), h1 = __float2bfloat16(v.y);
    __nv_bfloat16 h2 = __float2bfloat16(v.z), h3 = __float2bfloat16(v.w);
    __nv_bfloat16 l0 = __float2bfloat16(v.x - __bfloat162float(h0));
    __nv_bfloat16 l1 = __float2bfloat16(v.y - __bfloat162float(h1));
    __nv_bfloat16 l2 = __float2bfloat16(v.z - __bfloat162float(h2));
    __nv_bfloat16 l3 = __float2bfloat16(v.w - __bfloat162float(h3));
    __nv_bfloat16* base = g_Bbf + (size_t)n * KSPLIT + k4;
    ((__nv_bfloat162*)(base))[0]        = __halves2bfloat162(h0, h1);
    ((__nv_bfloat162*)(base))[1]        = __halves2bfloat162(h2, h3);
    ((__nv_bfloat162*)(base + 1024))[0] = __halves2bfloat162(h0, h1);
    ((__nv_bfloat162*)(base + 1024))[1] = __halves2bfloat162(h2, h3);
    ((__nv_bfloat162*)(base + 2048))[0] = __halves2bfloat162(l0, l1);
    ((__nv_bfloat162*)(base + 2048))[1] = __halves2bfloat162(l2, l3);
}

// ---------------- tau kernel ----------------
__global__ __launch_bounds__(128) void tau_kernel(
    const float* __restrict__ x,
    const float* __restrict__ w_attn, const float* __restrict__ b_attn,
    const float* __restrict__ w_know, const float* __restrict__ b_know)
{
    int r = blockIdx.x;
    const float* xr = x + (size_t)r * D_DIM;
    float s0 = 0.f, s1 = 0.f, s2 = 0.f, s3 = 0.f;
    for (int d = threadIdx.x; d < D_DIM; d += 128) {
        float xv = xr[d];
        s0 += xv * w_attn[d * 3 + 0];
        s1 += xv * w_attn[d * 3 + 1];
        s2 += xv * w_attn[d * 3 + 2];
        s3 += xv * w_know[d];
    }
    __shared__ float red[4][128];
    red[0][threadIdx.x] = s0; red[1][threadIdx.x] = s1;
    red[2][threadIdx.x] = s2; red[3][threadIdx.x] = s3;
    __syncthreads();
    for (int off = 64; off > 0; off >>= 1) {
        if (threadIdx.x < off) {
            red[0][threadIdx.x] += red[0][threadIdx.x + off];
            red[1][threadIdx.x] += red[1][threadIdx.x + off];
            red[2][threadIdx.x] += red[2][threadIdx.x + off];
            red[3][threadIdx.x] += red[3][threadIdx.x + off];
        }
        __syncthreads();
    }
    if (threadIdx.x == 0) {
        g_tau[r * 4 + 0] = red[0][0] + b_attn[0];
        g_tau[r * 4 + 1] = red[1][0] + b_attn[1];
        g_tau[r * 4 + 2] = red[2][0] + b_attn[2];
        g_tau[r * 4 + 3] = red[3][0] + b_know[0];
    }
}

// ---------------- mma.sync bf16 GEMM (exact champion config) ----------------
#define STG_SZ  20480                 // A (10240) + B (10240) per stage
#define NSTAGE  3
#define KITERS  (KSPLIT / 32)         // 96
#define GEMM_SMEM (NSTAGE * STG_SZ)   // 61440

__device__ __forceinline__ void gemm_load_stage(uint32_t sbase,
    const __nv_bfloat16* gA, const __nv_bfloat16* gB, int kit, int s, int tid)
{
    const int k0 = kit * 32;
    const uint32_t st = sbase + s * STG_SZ;
#pragma unroll
    for (int i = 0; i < 2; i++) {
        int c = tid + i * 256;
        int row = c >> 2, c4 = c & 3;
        CP_ASYNC16(st + row * 80 + c4 * 16,
                   gA + (size_t)row * KSPLIT + k0 + c4 * 8);
    }
#pragma unroll
    for (int i = 0; i < 2; i++) {
        int c = tid + i * 256;
        int row = c >> 2, c4 = c & 3;
        CP_ASYNC16(st + 10240 + row * 80 + c4 * 16,
                   gB + (size_t)row * KSPLIT + k0 + c4 * 8);
    }
}

__global__ __launch_bounds__(256, 2) void gemm_bf16_kernel() {
    extern __shared__ __align__(128) char smem[];
    const uint32_t sbase = smem_u32(smem);
    const int tid = threadIdx.x;
    const int wid = tid >> 5;
    const int lid = tid & 31;
    const int m0 = blockIdx.x * 128;
    const int n0 = blockIdx.y * 128;
    const int wm = wid & 1;
    const int wn = wid >> 1;

    const __nv_bfloat16* gA = g_Abf + (size_t)m0 * KSPLIT;
    const __nv_bfloat16* gB = g_Bbf + (size_t)n0 * KSPLIT;

    const int arow = (lid & 7) + ((lid >> 3) & 1) * 8;
    const int acol = (lid >> 4) * 8;
    const int brow = lid & 7;
    const int bcol = ((lid >> 3) & 1) * 8;

    float acc[4][4][4];
#pragma unroll
    for (int i = 0; i < 4; i++)
#pragma unroll
        for (int j = 0; j < 4; j++)
#pragma unroll
            for (int q = 0; q < 4; q++) acc[i][j][q] = 0.f;

    gemm_load_stage(sbase, gA, gB, 0, 0, tid); CP_COMMIT();
    gemm_load_stage(sbase, gA, gB, 1, 1, tid); CP_COMMIT();

#pragma unroll 1
    for (int k = 0; k < KITERS; k++) {
        const int s = k % NSTAGE;
        if (k < KITERS - 2) asm volatile("cp.async.wait_group 1;");
        else                asm volatile("cp.async.wait_group 0;");
        __syncthreads();

        const uint32_t sA = sbase + s * STG_SZ;
        const uint32_t sB = sA + 10240;
#pragma unroll
        for (int ks = 0; ks < 2; ks++) {
            const int kb = ks * 16;
            uint32_t a[4][4], b[4][2];
            const uint32_t a_base = sA + (uint32_t)(wm * 64 + arow) * 80u + (uint32_t)(kb + acol) * 2u;
#pragma unroll
            for (int i = 0; i < 4; i++)
                ldmatrix_x4(a[i][0], a[i][1], a[i][2], a[i][3], a_base + (uint32_t)(i * 16 * 80));
            const uint32_t b_base = sB + (uint32_t)(wn * 32 + brow) * 80u + (uint32_t)(kb + bcol) * 2u;
#pragma unroll
            for (int j = 0; j < 4; j++)
                ldmatrix_x2(b[j][0], b[j][1], b_base + (uint32_t)(j * 8 * 80));
#pragma unroll
            for (int i = 0; i < 4; i++)
#pragma unroll
                for (int j = 0; j < 4; j++)
                    mma_bf16(acc[i][j], a[i], b[j]);
        }

        if (k + 2 < KITERS) {
            gemm_load_stage(sbase, gA, gB, k + 2, (k + 2) % NSTAGE, tid);
            CP_COMMIT();
        }
    }

    const int r4 = lid >> 2;
    const int c2 = (lid & 3) * 2;
#pragma unroll
    for (int i = 0; i < 4; i++) {
#pragma unroll
        for (int j = 0; j < 4; j++) {
            int row = m0 + wm * 64 + i * 16 + r4;
            int col = n0 + wn * 32 + j * 8 + c2;
            float* p0 = g_scores + (size_t)row * NTOT + col;
            float* p1 = g_scores + (size_t)(row + 8) * NTOT + col;
            *(float2*)p0 = make_float2(acc[i][j][0], acc[i][j][1]);
            *(float2*)p1 = make_float2(acc[i][j][2], acc[i][j][3]);
        }
    }
}

// ---------------- gate kernel (champion; warp-parallel bin selection) ----------------
template<int N, int KSEL>
__global__ __launch_bounds__(256) void gate_kernel(
    int seg_off, int tau_idx, int gate_id,
    float* __restrict__ out, int colsum_off)
{
    const int r = blockIdx.x;
    const float* s = g_scores + (size_t)r * NTOT + seg_off;
    const float tauv = g_tau[r * 4 + tau_idx];

    __shared__ float eg[N];
    __shared__ unsigned hist[256];
    __shared__ float red[256];
    __shared__ unsigned sh_sel;
    __shared__ int sh_kneed;
    __shared__ int sh_bandcnt;
    const int tid = threadIdx.x;
    const int wid = tid >> 5, lid = tid & 31;

    // Pass 1: exp_gate + global max
    float lmax = 0.f;
    for (int i = tid; i < N; i += 256) {
        float e = egate(s[i] - tauv);
        eg[i] = e;
        lmax = fmaxf(lmax, e);
    }
    red[tid] = lmax; __syncthreads();
    for (int off = 128; off > 0; off >>= 1) {
        if (tid < off) red[tid] = fmaxf(red[tid], red[tid + off]);
        __syncthreads();
    }
    const float gmax = red[0];
    __syncthreads();

    // radix select: exact k-th largest; bin resolution via warp-0 suffix scan
    unsigned prefix = 0u, mask = 0u;
    int kneed = KSEL;
    for (int shift = 24; shift >= 0; shift -= 8) {
        hist[tid] = 0u;
        __syncthreads();
        for (int i = tid; i < N; i += 256) {
            unsigned b = __float_as_uint(eg[i]);
            if ((b & mask) == prefix) atomicAdd(&hist[(b >> shift) & 0xFFu], 1u);
        }
        __syncthreads();
        if (wid == 0) {
            // lane l covers group g = 31-l -> bins [8g .. 8g+7]; lane order = descending bins
            const int g = 31 - lid;
            unsigned gs = 0;
#pragma unroll
            for (int b = 0; b < 8; b++) gs += hist[g * 8 + b];
            unsigned cum = gs;                       // inclusive suffix (from top) per lane
#pragma unroll
            for (int o = 1; o < 32; o <<= 1) {
                unsigned t = __shfl_up_sync(0xFFFFFFFFu, cum, o);
                if (lid >= o) cum += t;
            }
            unsigned ballot = __ballot_sync(0xFFFFFFFFu, cum >= (unsigned)kneed);
            int sel_lane = __ffs(ballot) - 1;        // first (lowest-lid) lane = highest bins
            if (lid == sel_lane) {
                unsigned before = cum - gs;          // count strictly above this group
                int kn = kneed - (int)before;
                unsigned c2 = 0; int selbin = g * 8; int newk = kn;
                for (int b = g * 8 + 7; b >= g * 8; b--) {
                    unsigned h = hist[b];
                    if (c2 + h >= (unsigned)kn) { selbin = b; newk = kn - (int)c2; break; }
                    c2 += h;
                }
                sh_sel = (unsigned)selbin; sh_kneed = newk;
            }
        }
        __syncthreads();
        prefix |= sh_sel << shift;
        mask   |= 0xFFu << shift;
        kneed   = sh_kneed;
        __syncthreads();
    }
    const float thr = __uint_as_float(prefix);

    // Ambiguity band detection
    bool need_fix = false;
    if (thr > THR_MIN) {
        float width = (thr + 1.0f) * BAND_RAW;
        float e_hi = thr + width, e_lo = thr - width;
        if (tid == 0) sh_bandcnt = 0;
        __syncthreads();
        int c = 0;
        for (int i = tid; i < N; i += 256) {
            float e = eg[i];
            if (e >= e_lo && e <= e_hi) c++;
        }
        if (c) atomicAdd(&sh_bandcnt, c);
        __syncthreads();
        need_fix = (sh_bandcnt > 1);
    }

    if (need_fix) {
        if (tid == 0) {
            int idx = atomicAdd(&g_fix_cnt, 1);
            if (idx < FIX_CAP) g_fix_items[idx] = r | (gate_id << 16);
        }
        return;  // fixup kernel rewrites this row entirely
    }

    // Pass 2: sum of kept entries
    float lsum = 0.f;
    for (int i = tid; i < N; i += 256) {
        float e = eg[i];
        if (e >= thr) lsum += e;
    }
    red[tid] = lsum; __syncthreads();
    for (int off = 128; off > 0; off >>= 1) {
        if (tid < off) red[tid] += red[tid + off];
        __syncthreads();
    }
    const float scale = __tanhf(gmax) / (red[0] + 1e-8f);

    // Pass 3: dense output + column sums
    float* orow = out + (size_t)r * N;
    for (int i = tid; i < N; i += 256) {
        float e = eg[i];
        float val = (e >= thr) ? e * scale : 0.f;
        orow[i] = val;
        if (e >= thr && e > 0.f) atomicAdd(&g_colsum[colsum_off + i], val);
    }
}

// ---------------- radix select for fixup (serial variant; rare path) ----------------
__device__ float radix_select_kth(const float* eg, int N, int ksel,
                                  unsigned* hist, unsigned* sh_sel, int* sh_kneed)
{
    const int tid = threadIdx.x;
    unsigned prefix = 0u, mask = 0u;
    int kneed = ksel;
    for (int shift = 24; shift >= 0; shift -= 8) {
        hist[tid] = 0u;
        __syncthreads();
        for (int i = tid; i < N; i += 256) {
            unsigned b = __float_as_uint(eg[i]);
            if ((b & mask) == prefix) atomicAdd(&hist[(b >> shift) & 0xFFu], 1u);
        }
        __syncthreads();
        if (tid == 0) {
            unsigned cum = 0u; int sel = 0; int newk = kneed;
            for (int bin = 255; bin >= 0; bin--) {
                unsigned h = hist[bin];
                if (cum + h >= (unsigned)kneed) { sel = bin; newk = kneed - (int)cum; break; }
                cum += h;
            }
            *sh_sel = (unsigned)sel; *sh_kneed = newk;
        }
        __syncthreads();
        prefix |= (*sh_sel) << shift;
        mask   |= 0xFFu << shift;
        kneed   = *sh_kneed;
        __syncthreads();
    }
    return __uint_as_float(prefix);
}

// ---------------- fixup kernel: exact fp64 re-ranking of ambiguous rows ----------------
__global__ __launch_bounds__(256) void fixup_kernel(
    const float* __restrict__ x,
    const float* __restrict__ qk, const float* __restrict__ vem, const float* __restrict__ knm,
    float* __restrict__ outQ, float* __restrict__ outK,
    float* __restrict__ outV, float* __restrict__ outKn)
{
    __shared__ float eg[NKNOW];
    __shared__ unsigned hist[256];
    __shared__ float red[256];
    __shared__ double dred[256];
    __shared__ unsigned sh_sel;
    __shared__ int sh_kneed;
    __shared__ int bidx[MAX_BAND];
    __shared__ double ds[MAX_BAND];
    __shared__ int keptm[MAX_BAND];
    __shared__ int sh_bc, sh_nhi;
    const int tid = threadIdx.x;

    int nfix = g_fix_cnt; if (nfix > FIX_CAP) nfix = FIX_CAP;

    for (int it = blockIdx.x; it < nfix; it += gridDim.x) {
        int code = g_fix_items[it];
        int r = code & 0xFFFF;
        int gate = code >> 16;

        int seg_off, N, ksel, tau_idx, cs_off;
        const float* emb; float* orow;
        if      (gate == 0) { seg_off = 0;        N = NQK;   ksel = 64;  tau_idx = 0; emb = qk;  orow = outQ;  cs_off = 0; }
        else if (gate == 1) { seg_off = 0;        N = NQK;   ksel = 64;  tau_idx = 1; emb = qk;  orow = outK;  cs_off = NQK; }
        else if (gate == 2) { seg_off = NQK;      N = NV;    ksel = 64;  tau_idx = 2; emb = vem; orow = outV;  cs_off = 2 * NQK; }
        else                { seg_off = NQK + NV; N = NKNOW; ksel = 128; tau_idx = 3; emb = knm; orow = outKn; cs_off = 3 * NQK; }
        orow += (size_t)r * N;

        const float* s = g_scores + (size_t)r * NTOT + seg_off;
        const float tauv = g_tau[r * 4 + tau_idx];

        float lmax = 0.f;
        for (int i = tid; i < N; i += 256) {
            float e = egate(s[i] - tauv);
            eg[i] = e;
            lmax = fmaxf(lmax, e);
        }
        red[tid] = lmax; __syncthreads();
        for (int off = 128; off > 0; off >>= 1) {
            if (tid < off) red[tid] = fmaxf(red[tid], red[tid + off]);
            __syncthreads();
        }
        const float gmax = red[0];
        __syncthreads();

        const float thr = radix_select_kth(eg, N, ksel, hist, &sh_sel, &sh_kneed);
        const float width = (thr + 1.0f) * BAND_RAW;
        const float e_hi = thr + width, e_lo = thr - width;

        if (tid == 0) { sh_bc = 0; sh_nhi = 0; }
        __syncthreads();
        for (int i = tid; i < N; i += 256) {
            float e = eg[i];
            if (e > e_hi) atomicAdd(&sh_nhi, 1);
            else if (e >= e_lo) {
                int p = atomicAdd(&sh_bc, 1);
                if (p < MAX_BAND) bidx[p] = i;
            }
        }
        __syncthreads();
        const int bc = (sh_bc < MAX_BAND) ? sh_bc : MAX_BAND;
        const int nhi = sh_nhi;

        const float* xr = x + (size_t)r * D_DIM;
        for (int b = 0; b < bc; b++) {
            const float* er = emb + (size_t)bidx[b] * D_DIM;
            double part = 0.0;
            for (int d = tid; d < D_DIM; d += 256)
                part += (double)xr[d] * (double)er[d];
            dred[tid] = part; __syncthreads();
            for (int off = 128; off > 0; off >>= 1) {
                if (tid < off) dred[tid] += dred[tid + off];
                __syncthreads();
            }
            if (tid == 0) ds[b] = dred[0];
            __syncthreads();
        }

        if (tid == 0) {
            int need = ksel - nhi;
            for (int j = 0; j < bc; j++) {
                int rank = 0;
                for (int m = 0; m < bc; m++) if (ds[m] > ds[j]) rank++;
                keptm[j] = (rank < need) ? 1 : 0;
            }
        }
        __syncthreads();

        float lsum = 0.f;
        for (int i = tid; i < N; i += 256) {
            float e = eg[i];
            if (e > e_hi) lsum += e;
        }
        if (tid == 0) {
            for (int b = 0; b < bc; b++)
                if (keptm[b]) lsum += eg[bidx[b]];
        }
        red[tid] = lsum; __syncthreads();
        for (int off = 128; off > 0; off >>= 1) {
            if (tid < off) red[tid] += red[tid + off];
            __syncthreads();
        }
        const float scale = __tanhf(gmax) / (red[0] + 1e-8f);

        for (int i = tid; i < N; i += 256) {
            float e = eg[i];
            bool keep = false;
            if (e > e_hi) keep = true;
            else if (e >= e_lo) {
                for (int b = 0; b < bc; b++)
                    if (bidx[b] == i) { keep = (keptm[b] != 0); break; }
            }
            float val = keep ? e * scale : 0.f;
            orow[i] = val;
            if (keep && e > 0.f) atomicAdd(&g_colsum[cs_off + i], val);
        }
        __syncthreads();
    }
}

// ---------------- aux finish ----------------
__global__ __launch_bounds__(256) void aux_finish_kernel(
    int colsum_off, int N, float t, float* __restrict__ outscalar)
{
    int c = blockIdx.x * blockDim.x + threadIdx.x;
    float v = 0.f;
    if (c < N) {
        float m = g_colsum[colsum_off + c] * (1.0f / (float)MROWS) - t;
        v = m * m * (float)N;
    }
    __shared__ float red[256];
    red[threadIdx.x] = v; __syncthreads();
    for (int off = 128; off > 0; off >>= 1) {
        if (threadIdx.x < off) red[threadIdx.x] += red[threadIdx.x + off];
        __syncthreads();
    }
    if (threadIdx.x == 0) atomicAdd(outscalar, red[0]);
}

// ---------------- launch (exact champion structure: single stream) ----------------
extern "C" void kernel_launch(void* const* d_in, const int* in_sizes, int n_in,
                              void* d_out, int out_size) {
    const float* x      = (const float*)d_in[0];
    const float* qk     = (const float*)d_in[1];
    const float* v      = (const float*)d_in[2];
    const float* kn     = (const float*)d_in[3];
    const float* w_attn = (const float*)d_in[4];
    const float* b_attn = (const float*)d_in[5];
    const float* w_know = (const float*)d_in[6];
    const float* b_know = (const float*)d_in[7];
    float* out = (float*)d_out;

    const size_t MN  = (size_t)MROWS * NQK;
    const size_t gQ_off = 0;
    const size_t gK_off = MN;
    const size_t gV_off = 2 * MN;
    const size_t aux_attn_off = 3 * MN;
    const size_t gKn_off = aux_attn_off + 1;
    const size_t aux_know_off = gKn_off + (size_t)MROWS * NKNOW;

    cudaFuncSetAttribute(gemm_bf16_kernel, cudaFuncAttributeMaxDynamicSharedMemorySize, GEMM_SMEM);

    init_kernel<<<(NTOT + NKNOW + 255) / 256, 256>>>(out, aux_attn_off, aux_know_off);

    convertA_kernel<<<(MROWS * D_DIM / 4) / 256, 256>>>(x);
    convertB_kernel<<<(NTOT * D_DIM / 4) / 256, 256>>>(qk, v, kn);

    tau_kernel<<<MROWS, 128>>>(x, w_attn, b_attn, w_know, b_know);

    gemm_bf16_kernel<<<dim3(MROWS / 128, NTOT / 128), 256, GEMM_SMEM>>>();

    gate_kernel<NQK,   64 ><<<MROWS, 256>>>(0,        0, 0, out + gQ_off,  0);
    gate_kernel<NQK,   64 ><<<MROWS, 256>>>(0,        1, 1, out + gK_off,  NQK);
    gate_kernel<NV,    64 ><<<MROWS, 256>>>(NQK,      2, 2, out + gV_off,  2 * NQK);
    gate_kernel<NKNOW, 128><<<MROWS, 256>>>(NQK + NV, 3, 3, out + gKn_off, 3 * NQK);

    fixup_kernel<<<256, 256>>>(x, qk, v, kn,
                               out + gQ_off, out + gK_off, out + gV_off, out + gKn_off);

    aux_finish_kernel<<<NQK / 256,   256>>>(0,       NQK,   1.0f / NQK,   out + aux_attn_off);
    aux_finish_kernel<<<NQK / 256,   256>>>(NQK,     NQK,   1.0f / NQK,   out + aux_attn_off);
    aux_finish_kernel<<<NV / 256,    256>>>(2 * NQK, NV,    1.0f / NV,    out + aux_attn_off);
    aux_finish_kernel<<<NKNOW / 256, 256>>>(3 * NQK, NKNOW, 1.0f / NKNOW, out + aux_know_off);
}

// round 16
// speedup vs baseline: 1.2137x; 1.0160x over previous
#include <cuda_runtime.h>
#include <cuda_bf16.h>
#include <math.h>
#include <stdint.h>

// Problem constants (B=2, S=2048, D=1024; fixed-shape problem)
#define D_DIM   1024
#define NQK     4096
#define NV      4096
#define NKNOW   8192
#define NTOT    (NQK + NV + NKNOW)   // 16384
#define MROWS   4096                 // B*S
#define KSPLIT  3072                 // 3 x 1024 bf16-split K

#define BAND_RAW 3.1e-5f
#define THR_MIN  2e-4f
#define MAX_BAND 64
#define FIX_CAP  65536

// fast exp gate: exp(raw)-1 for raw>0 else 0 (MUFU path; discrepancies land in band -> fixup)
__device__ __forceinline__ float egate(float raw) {
    return (raw > 0.f) ? (__expf(raw) - 1.f) : 0.f;
}

// ---------------- scratch ----------------
__device__ float g_scores[(size_t)MROWS * NTOT];            // 268 MB
__device__ __nv_bfloat16 g_Abf[(size_t)MROWS * KSPLIT];     // 25 MB  [hi | lo | hi]
__device__ __nv_bfloat16 g_Bbf[(size_t)NTOT * KSPLIT];      // 100 MB [hi | hi | lo]
__device__ float g_tau[MROWS * 4];
__device__ float g_colsum[NTOT + NKNOW];
__device__ int   g_fix_cnt;
__device__ int   g_fix_items[FIX_CAP];

// ======================= PTX helpers (plain sm_103-safe) =======================
__device__ __forceinline__ uint32_t smem_u32(const void* p) {
    uint32_t a;
    asm("{ .reg .u64 t; cvta.to.shared.u64 t, %1; cvt.u32.u64 %0, t; }" : "=r"(a) : "l"(p));
    return a;
}
#define CP_ASYNC16(dst, src) \
    asm volatile("cp.async.cg.shared.global [%0], [%1], 16;" :: "r"(dst), "l"(src))
#define CP_COMMIT() asm volatile("cp.async.commit_group;")

__device__ __forceinline__ void ldmatrix_x4(uint32_t& r0, uint32_t& r1, uint32_t& r2, uint32_t& r3, uint32_t addr) {
    asm volatile("ldmatrix.sync.aligned.m8n8.x4.shared.b16 {%0,%1,%2,%3}, [%4];"
                 : "=r"(r0), "=r"(r1), "=r"(r2), "=r"(r3) : "r"(addr));
}
__device__ __forceinline__ void ldmatrix_x2(uint32_t& r0, uint32_t& r1, uint32_t addr) {
    asm volatile("ldmatrix.sync.aligned.m8n8.x2.shared.b16 {%0,%1}, [%2];"
                 : "=r"(r0), "=r"(r1) : "r"(addr));
}
__device__ __forceinline__ void mma_bf16(float* c, const uint32_t* a, const uint32_t* b) {
    asm volatile("mma.sync.aligned.m16n8k16.row.col.f32.bf16.bf16.f32 "
                 "{%0,%1,%2,%3}, {%4,%5,%6,%7}, {%8,%9}, {%0,%1,%2,%3};"
                 : "+f"(c[0]), "+f"(c[1]), "+f"(c[2]), "+f"(c[3])
                 : "r"(a[0]), "r"(a[1]), "r"(a[2]), "r"(a[3]), "r"(b[0]), "r"(b[1]));
}

// ---------------- init: zero colsums + fix counter + output scalars ----------------
__global__ void init_kernel(float* __restrict__ out, size_t aux_attn_off, size_t aux_know_off) {
    int i = blockIdx.x * blockDim.x + threadIdx.x;
    if (i < NTOT + NKNOW) g_colsum[i] = 0.f;
    if (i == 0) { out[aux_attn_off] = 0.f; out[aux_know_off] = 0.f; g_fix_cnt = 0; }
}

// ---------------- bf16-split conversion ----------------
__global__ __launch_bounds__(256) void convertA_kernel(const float* __restrict__ x) {
    int i = blockIdx.x * 256 + threadIdx.x;
    float4 v = ((const float4*)x)[i];
    int m = i >> 8;
    int k4 = (i & 255) << 2;
    __nv_bfloat16 h0 = __float2bfloat16(v.x), h1 = __float2bfloat16(v.y);
    __nv_bfloat16 h2 = __float2bfloat16(v.z), h3 = __float2bfloat16(v.w);
    __nv_bfloat16 l0 = __float2bfloat16(v.x - __bfloat162float(h0));
    __nv_bfloat16 l1 = __float2bfloat16(v.y - __bfloat162float(h1));
    __nv_bfloat16 l2 = __float2bfloat16(v.z - __bfloat162float(h2));
    __nv_bfloat16 l3 = __float2bfloat16(v.w - __bfloat162float(h3));
    __nv_bfloat16* base = g_Abf + (size_t)m * KSPLIT + k4;
    ((__nv_bfloat162*)(base))[0]        = __halves2bfloat162(h0, h1);
    ((__nv_bfloat162*)(base))[1]        = __halves2bfloat162(h2, h3);
    ((__nv_bfloat162*)(base + 1024))[0] = __halves2bfloat162(l0, l1);
    ((__nv_bfloat162*)(base + 1024))[1] = __halves2bfloat162(l2, l3);
    ((__nv_bfloat162*)(base + 2048))[0] = __halves2bfloat162(h0, h1);
    ((__nv_bfloat162*)(base + 2048))[1] = __halves2bfloat162(h2, h3);
}

__global__ __launch_bounds__(256) void convertB_kernel(
    const float* __restrict__ qk, const float* __restrict__ vem, const float* __restrict__ knm) {
    int i = blockIdx.x * 256 + threadIdx.x;
    int n = i >> 8;
    int k4 = (i & 255) << 2;
    const float* src;
    if (n < NQK)            src = qk  + (size_t)n * D_DIM;
    else if (n < NQK + NV)  src = vem + (size_t)(n - NQK) * D_DIM;
    else                    src = knm + (size_t)(n - NQK - NV) * D_DIM;
    float4 v = *(const float4*)(src + k4);
    __nv_bfloat16 h0 = __float2bfloat16(v.x), h1 = __float2bfloat16(v.y);
    __nv_bfloat16 h2 = __float2bfloat16(v.z), h3 = __float2bfloat16(v.w);
    __nv_bfloat16 l0 = __float2bfloat16(v.x - __bfloat162float(h0));
    __nv_bfloat16 l1 = __float2bfloat16(v.y - __bfloat162float(h1));
    __nv_bfloat16 l2 = __float2bfloat16(v.z - __bfloat162float(h2));
    __nv_bfloat16 l3 = __float2bfloat16(v.w - __bfloat162float(h3));
    __nv_bfloat16* base = g_Bbf + (size_t)n * KSPLIT + k4;
    ((__nv_bfloat162*)(base))[0]        = __halves2bfloat162(h0, h1);
    ((__nv_bfloat162*)(base))[1]        = __halves2bfloat162(h2, h3);
    ((__nv_bfloat162*)(base + 1024))[0] = __halves2bfloat162(h0, h1);
    ((__nv_bfloat162*)(base + 1024))[1] = __halves2bfloat162(h2, h3);
    ((__nv_bfloat162*)(base + 2048))[0] = __halves2bfloat162(l0, l1);
    ((__nv_bfloat162*)(base + 2048))[1] = __halves2bfloat162(l2, l3);
}

// ---------------- tau kernel ----------------
__global__ __launch_bounds__(128) void tau_kernel(
    const float* __restrict__ x,
    const float* __restrict__ w_attn, const float* __restrict__ b_attn,
    const float* __restrict__ w_know, const float* __restrict__ b_know)
{
    int r = blockIdx.x;
    const float* xr = x + (size_t)r * D_DIM;
    float s0 = 0.f, s1 = 0.f, s2 = 0.f, s3 = 0.f;
    for (int d = threadIdx.x; d < D_DIM; d += 128) {
        float xv = xr[d];
        s0 += xv * w_attn[d * 3 + 0];
        s1 += xv * w_attn[d * 3 + 1];
        s2 += xv * w_attn[d * 3 + 2];
        s3 += xv * w_know[d];
    }
    __shared__ float red[4][128];
    red[0][threadIdx.x] = s0; red[1][threadIdx.x] = s1;
    red[2][threadIdx.x] = s2; red[3][threadIdx.x] = s3;
    __syncthreads();
    for (int off = 64; off > 0; off >>= 1) {
        if (threadIdx.x < off) {
            red[0][threadIdx.x] += red[0][threadIdx.x + off];
            red[1][threadIdx.x] += red[1][threadIdx.x + off];
            red[2][threadIdx.x] += red[2][threadIdx.x + off];
            red[3][threadIdx.x] += red[3][threadIdx.x + off];
        }
        __syncthreads();
    }
    if (threadIdx.x == 0) {
        g_tau[r * 4 + 0] = red[0][0] + b_attn[0];
        g_tau[r * 4 + 1] = red[1][0] + b_attn[1];
        g_tau[r * 4 + 2] = red[2][0] + b_attn[2];
        g_tau[r * 4 + 3] = red[3][0] + b_know[0];
    }
}

// ---------------- mma.sync bf16 GEMM (exact champion config) ----------------
#define STG_SZ  20480                 // A (10240) + B (10240) per stage
#define NSTAGE  3
#define KITERS  (KSPLIT / 32)         // 96
#define GEMM_SMEM (NSTAGE * STG_SZ)   // 61440

__device__ __forceinline__ void gemm_load_stage(uint32_t sbase,
    const __nv_bfloat16* gA, const __nv_bfloat16* gB, int kit, int s, int tid)
{
    const int k0 = kit * 32;
    const uint32_t st = sbase + s * STG_SZ;
#pragma unroll
    for (int i = 0; i < 2; i++) {
        int c = tid + i * 256;
        int row = c >> 2, c4 = c & 3;
        CP_ASYNC16(st + row * 80 + c4 * 16,
                   gA + (size_t)row * KSPLIT + k0 + c4 * 8);
    }
#pragma unroll
    for (int i = 0; i < 2; i++) {
        int c = tid + i * 256;
        int row = c >> 2, c4 = c & 3;
        CP_ASYNC16(st + 10240 + row * 80 + c4 * 16,
                   gB + (size_t)row * KSPLIT + k0 + c4 * 8);
    }
}

__global__ __launch_bounds__(256, 2) void gemm_bf16_kernel() {
    extern __shared__ __align__(128) char smem[];
    const uint32_t sbase = smem_u32(smem);
    const int tid = threadIdx.x;
    const int wid = tid >> 5;
    const int lid = tid & 31;
    const int m0 = blockIdx.x * 128;
    const int n0 = blockIdx.y * 128;
    const int wm = wid & 1;
    const int wn = wid >> 1;

    const __nv_bfloat16* gA = g_Abf + (size_t)m0 * KSPLIT;
    const __nv_bfloat16* gB = g_Bbf + (size_t)n0 * KSPLIT;

    const int arow = (lid & 7) + ((lid >> 3) & 1) * 8;
    const int acol = (lid >> 4) * 8;
    const int brow = lid & 7;
    const int bcol = ((lid >> 3) & 1) * 8;

    float acc[4][4][4];
#pragma unroll
    for (int i = 0; i < 4; i++)
#pragma unroll
        for (int j = 0; j < 4; j++)
#pragma unroll
            for (int q = 0; q < 4; q++) acc[i][j][q] = 0.f;

    gemm_load_stage(sbase, gA, gB, 0, 0, tid); CP_COMMIT();
    gemm_load_stage(sbase, gA, gB, 1, 1, tid); CP_COMMIT();

#pragma unroll 1
    for (int k = 0; k < KITERS; k++) {
        const int s = k % NSTAGE;
        if (k < KITERS - 2) asm volatile("cp.async.wait_group 1;");
        else                asm volatile("cp.async.wait_group 0;");
        __syncthreads();

        const uint32_t sA = sbase + s * STG_SZ;
        const uint32_t sB = sA + 10240;
#pragma unroll
        for (int ks = 0; ks < 2; ks++) {
            const int kb = ks * 16;
            uint32_t a[4][4], b[4][2];
            const uint32_t a_base = sA + (uint32_t)(wm * 64 + arow) * 80u + (uint32_t)(kb + acol) * 2u;
#pragma unroll
            for (int i = 0; i < 4; i++)
                ldmatrix_x4(a[i][0], a[i][1], a[i][2], a[i][3], a_base + (uint32_t)(i * 16 * 80));
            const uint32_t b_base = sB + (uint32_t)(wn * 32 + brow) * 80u + (uint32_t)(kb + bcol) * 2u;
#pragma unroll
            for (int j = 0; j < 4; j++)
                ldmatrix_x2(b[j][0], b[j][1], b_base + (uint32_t)(j * 8 * 80));
#pragma unroll
            for (int i = 0; i < 4; i++)
#pragma unroll
                for (int j = 0; j < 4; j++)
                    mma_bf16(acc[i][j], a[i], b[j]);
        }

        if (k + 2 < KITERS) {
            gemm_load_stage(sbase, gA, gB, k + 2, (k + 2) % NSTAGE, tid);
            CP_COMMIT();
        }
    }

    const int r4 = lid >> 2;
    const int c2 = (lid & 3) * 2;
#pragma unroll
    for (int i = 0; i < 4; i++) {
#pragma unroll
        for (int j = 0; j < 4; j++) {
            int row = m0 + wm * 64 + i * 16 + r4;
            int col = n0 + wn * 32 + j * 8 + c2;
            float* p0 = g_scores + (size_t)row * NTOT + col;
            float* p1 = g_scores + (size_t)(row + 8) * NTOT + col;
            *(float2*)p0 = make_float2(acc[i][j][0], acc[i][j][1]);
            *(float2*)p1 = make_float2(acc[i][j][2], acc[i][j][3]);
        }
    }
}

// ---------------- gate kernel (fused hist0+load, fused band+sum, shuffle reductions) ----------------
template<int N, int KSEL>
__global__ __launch_bounds__(256) void gate_kernel(
    int seg_off, int tau_idx, int gate_id,
    float* __restrict__ out, int colsum_off)
{
    const int r = blockIdx.x;
    const float* s = g_scores + (size_t)r * NTOT + seg_off;
    const float tauv = g_tau[r * 4 + tau_idx];

    __shared__ float eg[N];
    __shared__ unsigned hist[256];
    __shared__ float s8f[8];
    __shared__ int   s8i[8];
    __shared__ unsigned sh_sel;
    __shared__ int sh_kneed;
    const int tid = threadIdx.x;
    const int wid = tid >> 5, lid = tid & 31;

    hist[tid] = 0u;
    __syncthreads();

    // Pass 1: load + exp_gate + max + digit-0 histogram (fused)
    float lmax = 0.f;
    for (int i = tid; i < N; i += 256) {
        float e = egate(s[i] - tauv);
        eg[i] = e;
        lmax = fmaxf(lmax, e);
        atomicAdd(&hist[__float_as_uint(e) >> 24], 1u);
    }
#pragma unroll
    for (int o = 16; o > 0; o >>= 1)
        lmax = fmaxf(lmax, __shfl_xor_sync(0xFFFFFFFFu, lmax, o));
    if (lid == 0) s8f[wid] = lmax;
    __syncthreads();
    const float gmax = fmaxf(fmaxf(fmaxf(s8f[0], s8f[1]), fmaxf(s8f[2], s8f[3])),
                             fmaxf(fmaxf(s8f[4], s8f[5]), fmaxf(s8f[6], s8f[7])));

    // digit 0 selection on the fused histogram (warp-0 suffix scan)
    if (wid == 0) {
        const int g = 31 - lid;
        unsigned gs = 0;
#pragma unroll
        for (int b = 0; b < 8; b++) gs += hist[g * 8 + b];
        unsigned cum = gs;
#pragma unroll
        for (int o = 1; o < 32; o <<= 1) {
            unsigned t = __shfl_up_sync(0xFFFFFFFFu, cum, o);
            if (lid >= o) cum += t;
        }
        unsigned ballot = __ballot_sync(0xFFFFFFFFu, cum >= (unsigned)KSEL);
        int sel_lane = __ffs(ballot) - 1;
        if (lid == sel_lane) {
            unsigned before = cum - gs;
            int kn = KSEL - (int)before;
            unsigned c2 = 0; int selbin = g * 8; int newk = kn;
            for (int b = g * 8 + 7; b >= g * 8; b--) {
                unsigned h = hist[b];
                if (c2 + h >= (unsigned)kn) { selbin = b; newk = kn - (int)c2; break; }
                c2 += h;
            }
            sh_sel = (unsigned)selbin; sh_kneed = newk;
        }
    }
    __syncthreads();
    unsigned prefix = sh_sel << 24;
    unsigned mask = 0xFF000000u;
    int kneed = sh_kneed;

    // digits 1..3
    for (int shift = 16; shift >= 0; shift -= 8) {
        hist[tid] = 0u;
        __syncthreads();
        for (int i = tid; i < N; i += 256) {
            unsigned b = __float_as_uint(eg[i]);
            if ((b & mask) == prefix) atomicAdd(&hist[(b >> shift) & 0xFFu], 1u);
        }
        __syncthreads();
        if (wid == 0) {
            const int g = 31 - lid;
            unsigned gs = 0;
#pragma unroll
            for (int b = 0; b < 8; b++) gs += hist[g * 8 + b];
            unsigned cum = gs;
#pragma unroll
            for (int o = 1; o < 32; o <<= 1) {
                unsigned t = __shfl_up_sync(0xFFFFFFFFu, cum, o);
                if (lid >= o) cum += t;
            }
            unsigned ballot = __ballot_sync(0xFFFFFFFFu, cum >= (unsigned)kneed);
            int sel_lane = __ffs(ballot) - 1;
            if (lid == sel_lane) {
                unsigned before = cum - gs;
                int kn = kneed - (int)before;
                unsigned c2 = 0; int selbin = g * 8; int newk = kn;
                for (int b = g * 8 + 7; b >= g * 8; b--) {
                    unsigned h = hist[b];
                    if (c2 + h >= (unsigned)kn) { selbin = b; newk = kn - (int)c2; break; }
                    c2 += h;
                }
                sh_sel = (unsigned)selbin; sh_kneed = newk;
            }
        }
        __syncthreads();
        prefix |= sh_sel << shift;
        mask   |= 0xFFu << shift;
        kneed   = sh_kneed;
    }
    const float thr = __uint_as_float(prefix);

    // Fused band + kept-sum scan
    const bool check_band = (thr > THR_MIN);
    const float width = (thr + 1.0f) * BAND_RAW;
    const float e_hi = thr + width, e_lo = thr - width;
    float lsum = 0.f;
    int bc = 0;
    for (int i = tid; i < N; i += 256) {
        float e = eg[i];
        if (e >= thr) lsum += e;
        if (check_band && e >= e_lo && e <= e_hi) bc++;
    }
#pragma unroll
    for (int o = 16; o > 0; o >>= 1) {
        lsum += __shfl_xor_sync(0xFFFFFFFFu, lsum, o);
        bc   += __shfl_xor_sync(0xFFFFFFFFu, bc, o);
    }
    __syncthreads();              // protect s8f reuse (gmax reads happened before radix syncs)
    if (lid == 0) { s8f[wid] = lsum; s8i[wid] = bc; }
    __syncthreads();
    const float gsum = s8f[0] + s8f[1] + s8f[2] + s8f[3] + s8f[4] + s8f[5] + s8f[6] + s8f[7];
    const int bandcnt = s8i[0] + s8i[1] + s8i[2] + s8i[3] + s8i[4] + s8i[5] + s8i[6] + s8i[7];

    if (check_band && bandcnt > 1) {
        if (tid == 0) {
            int idx = atomicAdd(&g_fix_cnt, 1);
            if (idx < FIX_CAP) g_fix_items[idx] = r | (gate_id << 16);
        }
        return;  // fixup kernel rewrites this row entirely
    }

    const float scale = __tanhf(gmax) / (gsum + 1e-8f);

    // Write pass: dense output + column sums
    float* orow = out + (size_t)r * N;
    for (int i = tid; i < N; i += 256) {
        float e = eg[i];
        float val = (e >= thr) ? e * scale : 0.f;
        orow[i] = val;
        if (e >= thr && e > 0.f) atomicAdd(&g_colsum[colsum_off + i], val);
    }
}

// ---------------- radix select for fixup (serial variant; rare path) ----------------
__device__ float radix_select_kth(const float* eg, int N, int ksel,
                                  unsigned* hist, unsigned* sh_sel, int* sh_kneed)
{
    const int tid = threadIdx.x;
    unsigned prefix = 0u, mask = 0u;
    int kneed = ksel;
    for (int shift = 24; shift >= 0; shift -= 8) {
        hist[tid] = 0u;
        __syncthreads();
        for (int i = tid; i < N; i += 256) {
            unsigned b = __float_as_uint(eg[i]);
            if ((b & mask) == prefix) atomicAdd(&hist[(b >> shift) & 0xFFu], 1u);
        }
        __syncthreads();
        if (tid == 0) {
            unsigned cum = 0u; int sel = 0; int newk = kneed;
            for (int bin = 255; bin >= 0; bin--) {
                unsigned h = hist[bin];
                if (cum + h >= (unsigned)kneed) { sel = bin; newk = kneed - (int)cum; break; }
                cum += h;
            }
            *sh_sel = (unsigned)sel; *sh_kneed = newk;
        }
        __syncthreads();
        prefix |= (*sh_sel) << shift;
        mask   |= 0xFFu << shift;
        kneed   = *sh_kneed;
        __syncthreads();
    }
    return __uint_as_float(prefix);
}

// ---------------- fixup kernel: exact fp64 re-ranking of ambiguous rows ----------------
__global__ __launch_bounds__(256) void fixup_kernel(
    const float* __restrict__ x,
    const float* __restrict__ qk, const float* __restrict__ vem, const float* __restrict__ knm,
    float* __restrict__ outQ, float* __restrict__ outK,
    float* __restrict__ outV, float* __restrict__ outKn)
{
    __shared__ float eg[NKNOW];
    __shared__ unsigned hist[256];
    __shared__ float red[256];
    __shared__ double dred[256];
    __shared__ unsigned sh_sel;
    __shared__ int sh_kneed;
    __shared__ int bidx[MAX_BAND];
    __shared__ double ds[MAX_BAND];
    __shared__ int keptm[MAX_BAND];
    __shared__ int sh_bc, sh_nhi;
    const int tid = threadIdx.x;

    int nfix = g_fix_cnt; if (nfix > FIX_CAP) nfix = FIX_CAP;

    for (int it = blockIdx.x; it < nfix; it += gridDim.x) {
        int code = g_fix_items[it];
        int r = code & 0xFFFF;
        int gate = code >> 16;

        int seg_off, N, ksel, tau_idx, cs_off;
        const float* emb; float* orow;
        if      (gate == 0) { seg_off = 0;        N = NQK;   ksel = 64;  tau_idx = 0; emb = qk;  orow = outQ;  cs_off = 0; }
        else if (gate == 1) { seg_off = 0;        N = NQK;   ksel = 64;  tau_idx = 1; emb = qk;  orow = outK;  cs_off = NQK; }
        else if (gate == 2) { seg_off = NQK;      N = NV;    ksel = 64;  tau_idx = 2; emb = vem; orow = outV;  cs_off = 2 * NQK; }
        else                { seg_off = NQK + NV; N = NKNOW; ksel = 128; tau_idx = 3; emb = knm; orow = outKn; cs_off = 3 * NQK; }
        orow += (size_t)r * N;

        const float* s = g_scores + (size_t)r * NTOT + seg_off;
        const float tauv = g_tau[r * 4 + tau_idx];

        float lmax = 0.f;
        for (int i = tid; i < N; i += 256) {
            float e = egate(s[i] - tauv);
            eg[i] = e;
            lmax = fmaxf(lmax, e);
        }
        red[tid] = lmax; __syncthreads();
        for (int off = 128; off > 0; off >>= 1) {
            if (tid < off) red[tid] = fmaxf(red[tid], red[tid + off]);
            __syncthreads();
        }
        const float gmax = red[0];
        __syncthreads();

        const float thr = radix_select_kth(eg, N, ksel, hist, &sh_sel, &sh_kneed);
        const float width = (thr + 1.0f) * BAND_RAW;
        const float e_hi = thr + width, e_lo = thr - width;

        if (tid == 0) { sh_bc = 0; sh_nhi = 0; }
        __syncthreads();
        for (int i = tid; i < N; i += 256) {
            float e = eg[i];
            if (e > e_hi) atomicAdd(&sh_nhi, 1);
            else if (e >= e_lo) {
                int p = atomicAdd(&sh_bc, 1);
                if (p < MAX_BAND) bidx[p] = i;
            }
        }
        __syncthreads();
        const int bc = (sh_bc < MAX_BAND) ? sh_bc : MAX_BAND;
        const int nhi = sh_nhi;

        const float* xr = x + (size_t)r * D_DIM;
        for (int b = 0; b < bc; b++) {
            const float* er = emb + (size_t)bidx[b] * D_DIM;
            double part = 0.0;
            for (int d = tid; d < D_DIM; d += 256)
                part += (double)xr[d] * (double)er[d];
            dred[tid] = part; __syncthreads();
            for (int off = 128; off > 0; off >>= 1) {
                if (tid < off) dred[tid] += dred[tid + off];
                __syncthreads();
            }
            if (tid == 0) ds[b] = dred[0];
            __syncthreads();
        }

        if (tid == 0) {
            int need = ksel - nhi;
            for (int j = 0; j < bc; j++) {
                int rank = 0;
                for (int m = 0; m < bc; m++) if (ds[m] > ds[j]) rank++;
                keptm[j] = (rank < need) ? 1 : 0;
            }
        }
        __syncthreads();

        float lsum = 0.f;
        for (int i = tid; i < N; i += 256) {
            float e = eg[i];
            if (e > e_hi) lsum += e;
        }
        if (tid == 0) {
            for (int b = 0; b < bc; b++)
                if (keptm[b]) lsum += eg[bidx[b]];
        }
        red[tid] = lsum; __syncthreads();
        for (int off = 128; off > 0; off >>= 1) {
            if (tid < off) red[tid] += red[tid + off];
            __syncthreads();
        }
        const float scale = __tanhf(gmax) / (red[0] + 1e-8f);

        for (int i = tid; i < N; i += 256) {
            float e = eg[i];
            bool keep = false;
            if (e > e_hi) keep = true;
            else if (e >= e_lo) {
                for (int b = 0; b < bc; b++)
                    if (bidx[b] == i) { keep = (keptm[b] != 0); break; }
            }
            float val = keep ? e * scale : 0.f;
            orow[i] = val;
            if (keep && e > 0.f) atomicAdd(&g_colsum[cs_off + i], val);
        }
        __syncthreads();
    }
}

// ---------------- aux finish ----------------
__global__ __launch_bounds__(256) void aux_finish_kernel(
    int colsum_off, int N, float t, float* __restrict__ outscalar)
{
    int c = blockIdx.x * blockDim.x + threadIdx.x;
    float v = 0.f;
    if (c < N) {
        float m = g_colsum[colsum_off + c] * (1.0f / (float)MROWS) - t;
        v = m * m * (float)N;
    }
    __shared__ float red[256];
    red[threadIdx.x] = v; __syncthreads();
    for (int off = 128; off > 0; off >>= 1) {
        if (threadIdx.x < off) red[threadIdx.x] += red[threadIdx.x + off];
        __syncthreads();
    }
    if (threadIdx.x == 0) atomicAdd(outscalar, red[0]);
}

// ---------------- launch (exact champion structure: single stream) ----------------
extern "C" void kernel_launch(void* const* d_in, const int* in_sizes, int n_in,
                              void* d_out, int out_size) {
    const float* x      = (const float*)d_in[0];
    const float* qk     = (const float*)d_in[1];
    const float* v      = (const float*)d_in[2];
    const float* kn     = (const float*)d_in[3];
    const float* w_attn = (const float*)d_in[4];
    const float* b_attn = (const float*)d_in[5];
    const float* w_know = (const float*)d_in[6];
    const float* b_know = (const float*)d_in[7];
    float* out = (float*)d_out;

    const size_t MN  = (size_t)MROWS * NQK;
    const size_t gQ_off = 0;
    const size_t gK_off = MN;
    const size_t gV_off = 2 * MN;
    const size_t aux_attn_off = 3 * MN;
    const size_t gKn_off = aux_attn_off + 1;
    const size_t aux_know_off = gKn_off + (size_t)MROWS * NKNOW;

    cudaFuncSetAttribute(gemm_bf16_kernel, cudaFuncAttributeMaxDynamicSharedMemorySize, GEMM_SMEM);

    init_kernel<<<(NTOT + NKNOW + 255) / 256, 256>>>(out, aux_attn_off, aux_know_off);

    convertA_kernel<<<(MROWS * D_DIM / 4) / 256, 256>>>(x);
    convertB_kernel<<<(NTOT * D_DIM / 4) / 256, 256>>>(qk, v, kn);

    tau_kernel<<<MROWS, 128>>>(x, w_attn, b_attn, w_know, b_know);

    gemm_bf16_kernel<<<dim3(MROWS / 128, NTOT / 128), 256, GEMM_SMEM>>>();

    gate_kernel<NQK,   64 ><<<MROWS, 256>>>(0,        0, 0, out + gQ_off,  0);
    gate_kernel<NQK,   64 ><<<MROWS, 256>>>(0,        1, 1, out + gK_off,  NQK);
    gate_kernel<NV,    64 ><<<MROWS, 256>>>(NQK,      2, 2, out + gV_off,  2 * NQK);
    gate_kernel<NKNOW, 128><<<MROWS, 256>>>(NQK + NV, 3, 3, out + gKn_off, 3 * NQK);

    fixup_kernel<<<256, 256>>>(x, qk, v, kn,
                               out + gQ_off, out + gK_off, out + gV_off, out + gKn_off);

    aux_finish_kernel<<<NQK / 256,   256>>>(0,       NQK,   1.0f / NQK,   out + aux_attn_off);
    aux_finish_kernel<<<NQK / 256,   256>>>(NQK,     NQK,   1.0f / NQK,   out + aux_attn_off);
    aux_finish_kernel<<<NV / 256,    256>>>(2 * NQK, NV,    1.0f / NV,    out + aux_attn_off);
    aux_finish_kernel<<<NKNOW / 256, 256>>>(3 * NQK, NKNOW, 1.0f / NKNOW, out + aux_know_off);
}